// round 11
// baseline (speedup 1.0000x reference)
#include <cuda_runtime.h>
#include <cuda_bf16.h>
#include <stdint.h>
#include <math.h>

#define SS 8192
#define DD 1024
#define HH 16
#define HDIM 64

// ---- scratch: bf16 hi/lo pairs (static device arrays) ----
__device__ __nv_bfloat16 g_xh[SS * DD], g_xl[SS * DD];
__device__ __nv_bfloat16 g_Wh[4][DD * DD], g_Wl[4][DD * DD];
__device__ __nv_bfloat16 g_Qh[SS * DD], g_Ql[SS * DD];
__device__ __nv_bfloat16 g_Kh[SS * DD], g_Kl[SS * DD];
__device__ __nv_bfloat16 g_Vh[SS * DD], g_Vl[SS * DD];
__device__ __nv_bfloat16 g_Oh[SS * DD], g_Ol[SS * DD];

// ===========================================================================
// PTX helpers (baseline ISA: ldmatrix + mma.sync + cp.async, sm_80+)
// ===========================================================================
__device__ __forceinline__ uint32_t smem_u32(const void* p) {
    uint32_t a;
    asm("{ .reg .u64 t; cvta.to.shared.u64 t, %1; cvt.u32.u64 %0, t; }"
        : "=r"(a) : "l"(p));
    return a;
}

#define LDSM_X4(r0, r1, r2, r3, addr)                                       \
    asm volatile(                                                           \
        "ldmatrix.sync.aligned.m8n8.x4.shared.b16 {%0, %1, %2, %3}, [%4];"  \
        : "=r"(r0), "=r"(r1), "=r"(r2), "=r"(r3) : "r"(addr))

#define LDSM_X4_T(r0, r1, r2, r3, addr)                                     \
    asm volatile(                                                           \
        "ldmatrix.sync.aligned.m8n8.x4.trans.shared.b16 {%0, %1, %2, %3}, [%4];" \
        : "=r"(r0), "=r"(r1), "=r"(r2), "=r"(r3) : "r"(addr))

#define MMA16816(d, a, b)                                                   \
    asm volatile(                                                           \
        "mma.sync.aligned.m16n8k16.row.col.f32.bf16.bf16.f32 "              \
        "{%0, %1, %2, %3}, {%4, %5, %6, %7}, {%8, %9}, {%0, %1, %2, %3};"   \
        : "+f"((d)[0]), "+f"((d)[1]), "+f"((d)[2]), "+f"((d)[3])            \
        : "r"((a)[0]), "r"((a)[1]), "r"((a)[2]), "r"((a)[3]),               \
          "r"((b)[0]), "r"((b)[1]))

#define CPA16(dst, src, sz)                                                 \
    asm volatile("cp.async.cg.shared.global [%0], [%1], 16, %2;"            \
                 :: "r"(dst), "l"(src), "r"(sz))
#define CPA_COMMIT() asm volatile("cp.async.commit_group;" ::: "memory")
#define CPA_WAIT1()  asm volatile("cp.async.wait_group 1;" ::: "memory")
#define CPA_WAIT0()  asm volatile("cp.async.wait_group 0;" ::: "memory")

#define SWZ(o)   ((o) ^ (((o) >> 3) & 0x70))   // 128B rows
#define SWZ64(o) ((o) ^ (((o) >> 3) & 0x30))   // 64B rows

// Single-instruction bf16x2 pack: {lo=x, hi=y}, round-to-nearest.
__device__ __forceinline__ uint32_t packbf(float x, float y) {
    uint32_t r;
    asm("cvt.rn.bf16x2.f32 %0, %1, %2;" : "=r"(r) : "f"(y), "f"(x));
    return r;
}
// hi/lo split of a float pair: h = bf16x2(x,y); l = bf16x2 of residues.
__device__ __forceinline__ void split2(float x, float y,
                                       uint32_t& h, uint32_t& l) {
    h = packbf(x, y);
    float hx = __uint_as_float(h << 16);
    float hy = __uint_as_float(h & 0xffff0000u);
    l = packbf(x - hx, y - hy);
}

// ===========================================================================
// Fused fp32 -> bf16 hi/lo split for x + the 4 weight matrices (one launch).
// ===========================================================================
#define NX8 (SS * DD / 8)
#define NW8 (DD * DD / 8)

__global__ void split_all(const float* __restrict__ x,
                          const float* __restrict__ w0,
                          const float* __restrict__ w1,
                          const float* __restrict__ w2,
                          const float* __restrict__ w3,
                          __nv_bfloat16* __restrict__ xh,
                          __nv_bfloat16* __restrict__ xl,
                          __nv_bfloat16* __restrict__ Wh,
                          __nv_bfloat16* __restrict__ Wl) {
    int idx = blockIdx.x * blockDim.x + threadIdx.x;
    if (idx >= NX8 + 4 * NW8) return;
    const float* src;
    __nv_bfloat16 *dh, *dl;
    size_t off;
    if (idx < NX8) {
        src = x; dh = xh; dl = xl; off = idx;
    } else {
        int r = idx - NX8;
        int w = r >> 17;           // / NW8 (2^17)
        int o = r & (NW8 - 1);
        const float* ws[4] = {w0, w1, w2, w3};
        src = ws[w];
        dh = Wh + (size_t)w * DD * DD;
        dl = Wl + (size_t)w * DD * DD;
        off = o;
    }
    const float4* p = (const float4*)src + off * 2;
    float4 v0 = p[0], v1 = p[1];
    uint32_t h[4], l[4];
    split2(v0.x, v0.y, h[0], l[0]);
    split2(v0.z, v0.w, h[1], l[1]);
    split2(v1.x, v1.y, h[2], l[2]);
    split2(v1.z, v1.w, h[3], l[3]);
    ((uint4*)dh)[off] = *(uint4*)h;
    ((uint4*)dl)[off] = *(uint4*)l;
}

// ===========================================================================
// Shared GEMM core: mma.sync, bf16x3 emulated-fp32, 3-stage cp.async, occ 2.
//   C[m,n] = sum_k A[m,k]*W[n,k] + bias[n]
// CTA 128x128, K-chunk 32 (64B rows, SW64), 256 threads (8 warps 32m x 64n).
// Inner loop interleaves B-fragment ldmatrix with MMA issue (short liveness).
// ===========================================================================
#define G_ST(s)  (1024 + (s) * 32768)
#define G_AH 0
#define G_AL 8192
#define G_BH 16384
#define G_BL 24576
#define GEMM_SMEM (1024 + 3 * 32768)
#define NCHUNK 32

__device__ __forceinline__ void gemm_core(
    const __nv_bfloat16* __restrict__ Ah, const __nv_bfloat16* __restrict__ Al,
    const __nv_bfloat16* __restrict__ Bh, const __nv_bfloat16* __restrict__ Bl,
    const float* __restrict__ bias, float* __restrict__ C,
    __nv_bfloat16* __restrict__ Ch, __nv_bfloat16* __restrict__ Cl,
    bool splitout, char* sm) {
    const uint32_t sbase = smem_u32(sm);
    float* sbias = (float*)sm;

    const int tid = threadIdx.x;
    const int wid = tid >> 5, lane = tid & 31;
    const int n0 = blockIdx.x * 128, m0 = blockIdx.y * 128;

    if (tid < 128) sbias[tid] = bias[n0 + tid];

    const int wm = (wid & 3) * 32;
    const int wn = (wid >> 2) * 64;

    float acc[2][8][4];
#pragma unroll
    for (int mt = 0; mt < 2; mt++)
#pragma unroll
        for (int nt = 0; nt < 8; nt++)
#pragma unroll
            for (int e = 0; e < 4; e++) acc[mt][nt][e] = 0.f;

    const int cr = tid >> 1;
    const int hcE = (tid & 1) * 16;
    const int localr = lane & 7, sel = lane >> 3;

    const __nv_bfloat16* rowA_h = Ah + (size_t)(m0 + cr) * DD + hcE;
    const __nv_bfloat16* rowA_l = Al + (size_t)(m0 + cr) * DD + hcE;
    const __nv_bfloat16* rowB_h = Bh + (size_t)(n0 + cr) * DD + hcE;
    const __nv_bfloat16* rowB_l = Bl + (size_t)(n0 + cr) * DD + hcE;

#define G_STAGE(c, s)                                                       \
    do {                                                                    \
        const uint32_t stb = sbase + G_ST(s);                               \
        _Pragma("unroll")                                                   \
        for (int j = 0; j < 2; j++) {                                       \
            uint32_t off = SWZ64((uint32_t)(cr * 64 + hcE * 2 + 16 * j));   \
            CPA16(stb + G_AH + off, rowA_h + (size_t)(c) * 32 + 8 * j, 16); \
            CPA16(stb + G_AL + off, rowA_l + (size_t)(c) * 32 + 8 * j, 16); \
            CPA16(stb + G_BH + off, rowB_h + (size_t)(c) * 32 + 8 * j, 16); \
            CPA16(stb + G_BL + off, rowB_l + (size_t)(c) * 32 + 8 * j, 16); \
        }                                                                   \
        CPA_COMMIT();                                                       \
    } while (0)

    G_STAGE(0, 0);
    G_STAGE(1, 1);

    for (int c = 0; c < NCHUNK; c++) {
        const int s = c % 3;
        if (c + 1 < NCHUNK) CPA_WAIT1(); else CPA_WAIT0();
        __syncthreads();
        if (c + 2 < NCHUNK) G_STAGE(c + 2, (c + 2) % 3);

        const uint32_t stb = sbase + G_ST(s);
#pragma unroll
        for (int kk = 0; kk < 32; kk += 16) {
            uint32_t ah[2][4], al[2][4];
#pragma unroll
            for (int mt = 0; mt < 2; mt++) {
                const int row = wm + mt * 16 + localr + (sel & 1) * 8;
                const int kb = kk + (sel >> 1) * 8;
                const uint32_t off = SWZ64((uint32_t)(row * 64 + kb * 2));
                LDSM_X4(ah[mt][0], ah[mt][1], ah[mt][2], ah[mt][3],
                        stb + G_AH + off);
                LDSM_X4(al[mt][0], al[mt][1], al[mt][2], al[mt][3],
                        stb + G_AL + off);
            }
            // per-np: load 2 n-tiles of B (hi+lo) and consume immediately
#pragma unroll
            for (int np = 0; np < 4; np++) {
                const int row = wn + np * 16 + (sel >> 1) * 8 + localr;
                const int kb = kk + (sel & 1) * 8;
                const uint32_t off = SWZ64((uint32_t)(row * 64 + kb * 2));
                uint32_t h0, h1, h2, h3, l0, l1, l2, l3;
                LDSM_X4(h0, h1, h2, h3, stb + G_BH + off);
                LDSM_X4(l0, l1, l2, l3, stb + G_BL + off);
                uint32_t b0h[2] = {h0, h1}, b1h[2] = {h2, h3};
                uint32_t b0l[2] = {l0, l1}, b1l[2] = {l2, l3};
#pragma unroll
                for (int mt = 0; mt < 2; mt++) {
                    MMA16816(acc[mt][2 * np], ah[mt], b0h);
                    MMA16816(acc[mt][2 * np], ah[mt], b0l);
                    MMA16816(acc[mt][2 * np], al[mt], b0h);
                    MMA16816(acc[mt][2 * np + 1], ah[mt], b1h);
                    MMA16816(acc[mt][2 * np + 1], ah[mt], b1l);
                    MMA16816(acc[mt][2 * np + 1], al[mt], b1h);
                }
            }
        }
    }

    const int er = lane >> 2;
    const int ec = (lane & 3) * 2;
#pragma unroll
    for (int mt = 0; mt < 2; mt++) {
#pragma unroll
        for (int nt = 0; nt < 8; nt++) {
            const int ct = wn + nt * 8 + ec;
            const int row0 = m0 + wm + mt * 16 + er;
            float x0 = acc[mt][nt][0] + sbias[ct];
            float x1 = acc[mt][nt][1] + sbias[ct + 1];
            float x2 = acc[mt][nt][2] + sbias[ct];
            float x3 = acc[mt][nt][3] + sbias[ct + 1];
            const size_t i0 = (size_t)row0 * DD + n0 + ct;
            const size_t i1 = (size_t)(row0 + 8) * DD + n0 + ct;
            if (splitout) {
                uint32_t h0, l0u, h1, l1u;
                split2(x0, x1, h0, l0u);
                split2(x2, x3, h1, l1u);
                *(uint32_t*)&Ch[i0] = h0;
                *(uint32_t*)&Cl[i0] = l0u;
                *(uint32_t*)&Ch[i1] = h1;
                *(uint32_t*)&Cl[i1] = l1u;
            } else {
                float2 v0 = {x0, x1}, v1 = {x2, x3};
                *(float2*)&C[i0] = v0;
                *(float2*)&C[i1] = v1;
            }
        }
    }
#undef G_STAGE
}

// Fused Q/K/V projections: blockIdx.z selects the weight/bias/output triple.
struct QKVArgs {
    const __nv_bfloat16* Bh[3];
    const __nv_bfloat16* Bl[3];
    const float* bias[3];
    __nv_bfloat16* Ch[3];
    __nv_bfloat16* Cl[3];
};

__global__ __launch_bounds__(256, 2)
void gemm_qkv(const __nv_bfloat16* __restrict__ Ah,
              const __nv_bfloat16* __restrict__ Al, QKVArgs a) {
    extern __shared__ char sm[];
    const int w = blockIdx.z;
    gemm_core(Ah, Al, a.Bh[w], a.Bl[w], a.bias[w], nullptr,
              a.Ch[w], a.Cl[w], true, sm);
}

__global__ __launch_bounds__(256, 2)
void gemm_out(const __nv_bfloat16* __restrict__ Ah,
              const __nv_bfloat16* __restrict__ Al,
              const __nv_bfloat16* __restrict__ Bh,
              const __nv_bfloat16* __restrict__ Bl,
              const float* __restrict__ bias, float* __restrict__ C) {
    extern __shared__ char sm[];
    gemm_core(Ah, Al, Bh, Bl, bias, C, nullptr, nullptr, false, sm);
}

// ===========================================================================
// mma.sync sliding-window flash attention, bf16x3, 2-stage cp.async,
// online softmax (exp2 domain) in registers, interior-tile mask fast path.
// CTA = 128 queries x 1 head, 8 warps (16 q-rows each).
// ===========================================================================
#define A_QH 0
#define A_QL 16384
#define A_ST(s) (32768 + (s) * 32768)
#define A_KH 0
#define A_KL 8192
#define A_VH 16384
#define A_VL 24576
#define ATT_SMEM (32768 + 2 * 32768)
#define SC2 (0.125f * 1.44269504f)   // score scale folded with log2(e)

__global__ __launch_bounds__(256, 2)
void attn_mma(const __nv_bfloat16* __restrict__ Qh,
              const __nv_bfloat16* __restrict__ Ql,
              const __nv_bfloat16* __restrict__ Kh,
              const __nv_bfloat16* __restrict__ Kl,
              const __nv_bfloat16* __restrict__ Vh,
              const __nv_bfloat16* __restrict__ Vl,
              __nv_bfloat16* __restrict__ Oh,
              __nv_bfloat16* __restrict__ Ol) {
    extern __shared__ char sm[];
    const uint32_t sbase = smem_u32(sm);

    const int tid = threadIdx.x;
    const int wid = tid >> 5, lane = tid & 31;
    const int qs = blockIdx.x * 128;
    const int hoff = blockIdx.y * HDIM;
    const int localr = lane & 7, sel = lane >> 3;

    // ---- stage Q tile (128 x 64 bf16 hi/lo), swizzled 128B rows ----
    {
        const int r = tid >> 1;
        const int half = (tid & 1) * 32;
        const size_t g = (size_t)(qs + r) * DD + hoff + half;
#pragma unroll
        for (int j = 0; j < 4; j++) {
            uint32_t off = SWZ((uint32_t)(r * 128 + (half + 8 * j) * 2));
            *(uint4*)(sm + A_QH + off) = *(const uint4*)&Qh[g + 8 * j];
            *(uint4*)(sm + A_QL + off) = *(const uint4*)&Ql[g + 8 * j];
        }
    }

    const int t0v = max(0, (512 - qs + 63) / 64);
    const int t1v = min(18, (SS + 512 - qs) / 64);

    const int svr = tid >> 2;
    const int svc = (tid & 3) * 16;

#define A_STAGE(t, s)                                                       \
    do {                                                                    \
        const int kabs_ = qs - 512 + 64 * (t) + svr;                        \
        const size_t g_ = (size_t)kabs_ * DD + hoff + svc;                  \
        const uint32_t stb_ = sbase + A_ST(s);                              \
        _Pragma("unroll")                                                   \
        for (int j = 0; j < 2; j++) {                                       \
            uint32_t off = SWZ((uint32_t)(svr * 128 + (svc + 8 * j) * 2));  \
            CPA16(stb_ + A_KH + off, &Kh[g_ + 8 * j], 16u);                 \
            CPA16(stb_ + A_KL + off, &Kl[g_ + 8 * j], 16u);                 \
            CPA16(stb_ + A_VH + off, &Vh[g_ + 8 * j], 16u);                 \
            CPA16(stb_ + A_VL + off, &Vl[g_ + 8 * j], 16u);                 \
        }                                                                   \
        CPA_COMMIT();                                                       \
    } while (0)

    const int q0 = qs + 16 * wid + (lane >> 2);
    const int q1 = q0 + 8;

    float m0 = -1e30f, m1 = -1e30f, l0 = 0.f, l1 = 0.f;
    float oacc[8][4];
#pragma unroll
    for (int nt = 0; nt < 8; nt++)
#pragma unroll
        for (int e = 0; e < 4; e++) oacc[nt][e] = 0.f;

    A_STAGE(t0v, 0);

    for (int t = t0v; t < t1v; t++) {
        const int s = (t - t0v) & 1;
        const int kt = qs - 512 + 64 * t;
        CPA_WAIT0();
        __syncthreads();
        if (t + 1 < t1v) A_STAGE(t + 1, s ^ 1);

        const uint32_t stb = sbase + A_ST(s);

        // ---- QK^T: S (16q x 64k per warp), interleaved K loads/MMAs ----
        float sacc[8][4];
#pragma unroll
        for (int nt = 0; nt < 8; nt++)
#pragma unroll
            for (int e = 0; e < 4; e++) sacc[nt][e] = 0.f;

#pragma unroll
        for (int kk = 0; kk < 64; kk += 16) {
            uint32_t qhf[4], qlf[4];
            {
                const int row = 16 * wid + localr + (sel & 1) * 8;
                const int kb = kk + (sel >> 1) * 8;
                const uint32_t off = SWZ((uint32_t)(row * 128 + kb * 2));
                LDSM_X4(qhf[0], qhf[1], qhf[2], qhf[3], sbase + A_QH + off);
                LDSM_X4(qlf[0], qlf[1], qlf[2], qlf[3], sbase + A_QL + off);
            }
#pragma unroll
            for (int np = 0; np < 4; np++) {
                const int row = np * 16 + (sel >> 1) * 8 + localr;
                const int kb = kk + (sel & 1) * 8;
                const uint32_t off = SWZ((uint32_t)(row * 128 + kb * 2));
                uint32_t h0, h1, h2, h3, lo0, lo1, lo2, lo3;
                LDSM_X4(h0, h1, h2, h3, stb + A_KH + off);
                LDSM_X4(lo0, lo1, lo2, lo3, stb + A_KL + off);
                uint32_t k0h[2] = {h0, h1}, k1h[2] = {h2, h3};
                uint32_t k0l[2] = {lo0, lo1}, k1l[2] = {lo2, lo3};
                MMA16816(sacc[2 * np], qhf, k0h);
                MMA16816(sacc[2 * np], qhf, k0l);
                MMA16816(sacc[2 * np], qlf, k0h);
                MMA16816(sacc[2 * np + 1], qhf, k1h);
                MMA16816(sacc[2 * np + 1], qhf, k1l);
                MMA16816(sacc[2 * np + 1], qlf, k1h);
            }
        }

        // ---- scale to exp2 domain (+ window mask on edge tiles) + max ----
        float mx0 = -1e30f, mx1 = -1e30f;
        if (t < 2 || t > 15) {
            const int cb = kt + 2 * (lane & 3);
#pragma unroll
            for (int nt = 0; nt < 8; nt++) {
#pragma unroll
                for (int e = 0; e < 2; e++) {
                    const int kabs = cb + 8 * nt + e;
                    float s0 = ((kabs >= q0 - 512) & (kabs < q0 + 512))
                                   ? sacc[nt][e] * SC2 : -1e30f;
                    float s1 = ((kabs >= q1 - 512) & (kabs < q1 + 512))
                                   ? sacc[nt][e + 2] * SC2 : -1e30f;
                    sacc[nt][e] = s0; sacc[nt][e + 2] = s1;
                    mx0 = fmaxf(mx0, s0); mx1 = fmaxf(mx1, s1);
                }
            }
        } else {
#pragma unroll
            for (int nt = 0; nt < 8; nt++) {
#pragma unroll
                for (int e = 0; e < 2; e++) {
                    float s0 = sacc[nt][e] * SC2;
                    float s1 = sacc[nt][e + 2] * SC2;
                    sacc[nt][e] = s0; sacc[nt][e + 2] = s1;
                    mx0 = fmaxf(mx0, s0); mx1 = fmaxf(mx1, s1);
                }
            }
        }
        mx0 = fmaxf(mx0, __shfl_xor_sync(0xffffffffu, mx0, 1));
        mx0 = fmaxf(mx0, __shfl_xor_sync(0xffffffffu, mx0, 2));
        mx1 = fmaxf(mx1, __shfl_xor_sync(0xffffffffu, mx1, 1));
        mx1 = fmaxf(mx1, __shfl_xor_sync(0xffffffffu, mx1, 2));
        const float mn0 = fmaxf(m0, mx0), mn1 = fmaxf(m1, mx1);
        const float a0 = exp2f(m0 - mn0), a1 = exp2f(m1 - mn1);
        m0 = mn0; m1 = mn1;
        float rs0 = 0.f, rs1 = 0.f;
#pragma unroll
        for (int nt = 0; nt < 8; nt++) {
#pragma unroll
            for (int e = 0; e < 2; e++) {
                float p0 = (sacc[nt][e] > -5e29f) ? exp2f(sacc[nt][e] - mn0) : 0.f;
                float p1 = (sacc[nt][e + 2] > -5e29f) ? exp2f(sacc[nt][e + 2] - mn1) : 0.f;
                rs0 += p0; rs1 += p1;
                sacc[nt][e] = p0; sacc[nt][e + 2] = p1;
            }
        }
        l0 = l0 * a0 + rs0;
        l1 = l1 * a1 + rs1;
#pragma unroll
        for (int nt = 0; nt < 8; nt++) {
            oacc[nt][0] *= a0; oacc[nt][1] *= a0;
            oacc[nt][2] *= a1; oacc[nt][3] *= a1;
        }

        // ---- PV: O += P * V, interleaved V loads/MMAs ----
#pragma unroll
        for (int kc = 0; kc < 4; kc++) {
            uint32_t pah[4], pal[4];
            split2(sacc[2 * kc][0], sacc[2 * kc][1], pah[0], pal[0]);
            split2(sacc[2 * kc][2], sacc[2 * kc][3], pah[1], pal[1]);
            split2(sacc[2 * kc + 1][0], sacc[2 * kc + 1][1], pah[2], pal[2]);
            split2(sacc[2 * kc + 1][2], sacc[2 * kc + 1][3], pah[3], pal[3]);

#pragma unroll
            for (int ntp = 0; ntp < 4; ntp++) {
                const int key = 16 * kc + (sel & 1) * 8 + localr;
                const int dim = (2 * ntp + (sel >> 1)) * 8;
                const uint32_t off = SWZ((uint32_t)(key * 128 + dim * 2));
                uint32_t h0, h1, h2, h3, lo0, lo1, lo2, lo3;
                LDSM_X4_T(h0, h1, h2, h3, stb + A_VH + off);
                LDSM_X4_T(lo0, lo1, lo2, lo3, stb + A_VL + off);
                uint32_t v0h[2] = {h0, h1}, v1h[2] = {h2, h3};
                uint32_t v0l[2] = {lo0, lo1}, v1l[2] = {lo2, lo3};
                MMA16816(oacc[2 * ntp], pah, v0h);
                MMA16816(oacc[2 * ntp], pah, v0l);
                MMA16816(oacc[2 * ntp], pal, v0h);
                MMA16816(oacc[2 * ntp + 1], pah, v1h);
                MMA16816(oacc[2 * ntp + 1], pah, v1l);
                MMA16816(oacc[2 * ntp + 1], pal, v1h);
            }
        }
    }

    // ---- epilogue: normalize, blend weight, write bf16 hi/lo ----
    l0 += __shfl_xor_sync(0xffffffffu, l0, 1);
    l0 += __shfl_xor_sync(0xffffffffu, l0, 2);
    l1 += __shfl_xor_sync(0xffffffffu, l1, 1);
    l1 += __shfl_xor_sync(0xffffffffu, l1, 2);
    float w0 = 1.f, w1 = 1.f;
    if (q0 >= SS - 128) w0 = 1.f + (float)(q0 - (SS - 128)) * (1.f / 127.f);
    if (q1 >= SS - 128) w1 = 1.f + (float)(q1 - (SS - 128)) * (1.f / 127.f);
    const float sc0 = w0 / l0, sc1 = w1 / l1;
    const int ec = 2 * (lane & 3);
#pragma unroll
    for (int nt = 0; nt < 8; nt++) {
        const size_t i0 = (size_t)q0 * DD + hoff + 8 * nt + ec;
        const size_t i1 = (size_t)q1 * DD + hoff + 8 * nt + ec;
        uint32_t h0, l0u, h1, l1u;
        split2(oacc[nt][0] * sc0, oacc[nt][1] * sc0, h0, l0u);
        split2(oacc[nt][2] * sc1, oacc[nt][3] * sc1, h1, l1u);
        *(uint32_t*)&Oh[i0] = h0;
        *(uint32_t*)&Ol[i0] = l0u;
        *(uint32_t*)&Oh[i1] = h1;
        *(uint32_t*)&Ol[i1] = l1u;
    }
}

// ===========================================================================
extern "C" void kernel_launch(void* const* d_in, const int* in_sizes, int n_in,
                              void* d_out, int out_size) {
    const float* x = nullptr;
    const float* Wm[4] = {nullptr, nullptr, nullptr, nullptr};
    const float* bm[4] = {nullptr, nullptr, nullptr, nullptr};
    int nw = 0, nb = 0;
    for (int i = 0; i < n_in; i++) {
        const float* p = (const float*)d_in[i];
        if (in_sizes[i] == SS * DD) x = p;
        else if (in_sizes[i] == DD * DD) { if (nw < 4) Wm[nw++] = p; }
        else if (in_sizes[i] == DD) { if (nb < 4) bm[nb++] = p; }
    }
    float* out = (float*)d_out;

    __nv_bfloat16 *xh, *xl, *Wh, *Wl, *Qh, *Ql, *Kh, *Kl, *Vh, *Vl, *Oh, *Ol;
    cudaGetSymbolAddress((void**)&xh, g_xh);
    cudaGetSymbolAddress((void**)&xl, g_xl);
    cudaGetSymbolAddress((void**)&Wh, g_Wh);
    cudaGetSymbolAddress((void**)&Wl, g_Wl);
    cudaGetSymbolAddress((void**)&Qh, g_Qh);
    cudaGetSymbolAddress((void**)&Ql, g_Ql);
    cudaGetSymbolAddress((void**)&Kh, g_Kh);
    cudaGetSymbolAddress((void**)&Kl, g_Kl);
    cudaGetSymbolAddress((void**)&Vh, g_Vh);
    cudaGetSymbolAddress((void**)&Vl, g_Vl);
    cudaGetSymbolAddress((void**)&Oh, g_Oh);
    cudaGetSymbolAddress((void**)&Ol, g_Ol);

    // ---- fused split of x and all 4 weights (one launch) ----
    const int NTOT = NX8 + 4 * NW8;
    split_all<<<(NTOT + 255) / 256, 256>>>(x, Wm[0], Wm[1], Wm[2], Wm[3],
                                           xh, xl, Wh, Wl);

    cudaFuncSetAttribute(gemm_qkv, cudaFuncAttributeMaxDynamicSharedMemorySize,
                         GEMM_SMEM);
    cudaFuncSetAttribute(gemm_out, cudaFuncAttributeMaxDynamicSharedMemorySize,
                         GEMM_SMEM);
    cudaFuncSetAttribute(attn_mma, cudaFuncAttributeMaxDynamicSharedMemorySize,
                         ATT_SMEM);

    // ---- fused Q/K/V projections ----
    QKVArgs qa;
    qa.Bh[0] = Wh;                       qa.Bl[0] = Wl;
    qa.Bh[1] = Wh + (size_t)1 * DD * DD; qa.Bl[1] = Wl + (size_t)1 * DD * DD;
    qa.Bh[2] = Wh + (size_t)2 * DD * DD; qa.Bl[2] = Wl + (size_t)2 * DD * DD;
    qa.bias[0] = bm[0]; qa.bias[1] = bm[1]; qa.bias[2] = bm[2];
    qa.Ch[0] = Qh; qa.Cl[0] = Ql;
    qa.Ch[1] = Kh; qa.Cl[1] = Kl;
    qa.Ch[2] = Vh; qa.Cl[2] = Vl;

    dim3 qkvgrid(DD / 128, SS / 128, 3);
    gemm_qkv<<<qkvgrid, 256, GEMM_SMEM>>>(xh, xl, qa);

    attn_mma<<<dim3(SS / 128, HH), 256, ATT_SMEM>>>(Qh, Ql, Kh, Kl, Vh, Vl,
                                                    Oh, Ol);

    dim3 ogrid(DD / 128, SS / 128);
    gemm_out<<<ogrid, 256, GEMM_SMEM>>>(Oh, Ol, Wh + (size_t)3 * DD * DD,
                                        Wl + (size_t)3 * DD * DD, bm[3], out);
}

// round 12
// speedup vs baseline: 1.0152x; 1.0152x over previous
#include <cuda_runtime.h>
#include <cuda_bf16.h>
#include <stdint.h>
#include <math.h>

#define SS 8192
#define DD 1024
#define HH 16
#define HDIM 64

// ---- scratch: bf16 hi/lo pairs (static device arrays) ----
__device__ __nv_bfloat16 g_xh[SS * DD], g_xl[SS * DD];
__device__ __nv_bfloat16 g_Wh[4][DD * DD], g_Wl[4][DD * DD];
__device__ __nv_bfloat16 g_Qh[SS * DD], g_Ql[SS * DD];
__device__ __nv_bfloat16 g_Kh[SS * DD], g_Kl[SS * DD];
__device__ __nv_bfloat16 g_Vh[SS * DD], g_Vl[SS * DD];
__device__ __nv_bfloat16 g_Oh[SS * DD], g_Ol[SS * DD];

// ===========================================================================
// PTX helpers (baseline ISA: ldmatrix + mma.sync + cp.async, sm_80+)
// ===========================================================================
__device__ __forceinline__ uint32_t smem_u32(const void* p) {
    uint32_t a;
    asm("{ .reg .u64 t; cvta.to.shared.u64 t, %1; cvt.u32.u64 %0, t; }"
        : "=r"(a) : "l"(p));
    return a;
}

#define LDSM_X4(r0, r1, r2, r3, addr)                                       \
    asm volatile(                                                           \
        "ldmatrix.sync.aligned.m8n8.x4.shared.b16 {%0, %1, %2, %3}, [%4];"  \
        : "=r"(r0), "=r"(r1), "=r"(r2), "=r"(r3) : "r"(addr))

#define LDSM_X4_T(r0, r1, r2, r3, addr)                                     \
    asm volatile(                                                           \
        "ldmatrix.sync.aligned.m8n8.x4.trans.shared.b16 {%0, %1, %2, %3}, [%4];" \
        : "=r"(r0), "=r"(r1), "=r"(r2), "=r"(r3) : "r"(addr))

#define MMA16816(d, a, b)                                                   \
    asm volatile(                                                           \
        "mma.sync.aligned.m16n8k16.row.col.f32.bf16.bf16.f32 "              \
        "{%0, %1, %2, %3}, {%4, %5, %6, %7}, {%8, %9}, {%0, %1, %2, %3};"   \
        : "+f"((d)[0]), "+f"((d)[1]), "+f"((d)[2]), "+f"((d)[3])            \
        : "r"((a)[0]), "r"((a)[1]), "r"((a)[2]), "r"((a)[3]),               \
          "r"((b)[0]), "r"((b)[1]))

#define CPA16(dst, src, sz)                                                 \
    asm volatile("cp.async.cg.shared.global [%0], [%1], 16, %2;"            \
                 :: "r"(dst), "l"(src), "r"(sz))
#define CPA_COMMIT() asm volatile("cp.async.commit_group;" ::: "memory")
#define CPA_WAIT1()  asm volatile("cp.async.wait_group 1;" ::: "memory")
#define CPA_WAIT0()  asm volatile("cp.async.wait_group 0;" ::: "memory")

#define SWZ(o)   ((o) ^ (((o) >> 3) & 0x70))   // 128B rows
#define SWZ64(o) ((o) ^ (((o) >> 3) & 0x30))   // 64B rows

// Single-instruction bf16x2 pack: {lo=x, hi=y}, round-to-nearest.
__device__ __forceinline__ uint32_t packbf(float x, float y) {
    uint32_t r;
    asm("cvt.rn.bf16x2.f32 %0, %1, %2;" : "=r"(r) : "f"(y), "f"(x));
    return r;
}
// hi/lo split of a float pair: h = bf16x2(x,y); l = bf16x2 of residues.
__device__ __forceinline__ void split2(float x, float y,
                                       uint32_t& h, uint32_t& l) {
    h = packbf(x, y);
    float hx = __uint_as_float(h << 16);
    float hy = __uint_as_float(h & 0xffff0000u);
    l = packbf(x - hx, y - hy);
}

// ===========================================================================
// Fused fp32 -> bf16 hi/lo split for x + the 4 weight matrices (one launch).
// ===========================================================================
#define NX8 (SS * DD / 8)
#define NW8 (DD * DD / 8)

__global__ void split_all(const float* __restrict__ x,
                          const float* __restrict__ w0,
                          const float* __restrict__ w1,
                          const float* __restrict__ w2,
                          const float* __restrict__ w3,
                          __nv_bfloat16* __restrict__ xh,
                          __nv_bfloat16* __restrict__ xl,
                          __nv_bfloat16* __restrict__ Wh,
                          __nv_bfloat16* __restrict__ Wl) {
    int idx = blockIdx.x * blockDim.x + threadIdx.x;
    if (idx >= NX8 + 4 * NW8) return;
    const float* src;
    __nv_bfloat16 *dh, *dl;
    size_t off;
    if (idx < NX8) {
        src = x; dh = xh; dl = xl; off = idx;
    } else {
        int r = idx - NX8;
        int w = r >> 17;           // / NW8 (2^17)
        int o = r & (NW8 - 1);
        const float* ws[4] = {w0, w1, w2, w3};
        src = ws[w];
        dh = Wh + (size_t)w * DD * DD;
        dl = Wl + (size_t)w * DD * DD;
        off = o;
    }
    const float4* p = (const float4*)src + off * 2;
    float4 v0 = p[0], v1 = p[1];
    uint32_t h[4], l[4];
    split2(v0.x, v0.y, h[0], l[0]);
    split2(v0.z, v0.w, h[1], l[1]);
    split2(v1.x, v1.y, h[2], l[2]);
    split2(v1.z, v1.w, h[3], l[3]);
    ((uint4*)dh)[off] = *(uint4*)h;
    ((uint4*)dl)[off] = *(uint4*)l;
}

// ===========================================================================
// Shared GEMM core: mma.sync, bf16x3 emulated-fp32, 3-stage cp.async, occ 2.
//   C[m,n] = sum_k A[m,k]*W[n,k] + bias[n]
// CTA 128x128, K-chunk 32 (64B rows, SW64), 256 threads (8 warps 32m x 64n).
// MMAs issued PRODUCT-MAJOR: consecutive MMAs never share an accumulator,
// so HMMA RAW chains are fully pipelined at 4 warps/SMSP.
// ===========================================================================
#define G_ST(s)  (1024 + (s) * 32768)
#define G_AH 0
#define G_AL 8192
#define G_BH 16384
#define G_BL 24576
#define GEMM_SMEM (1024 + 3 * 32768)
#define NCHUNK 32

__device__ __forceinline__ void gemm_core(
    const __nv_bfloat16* __restrict__ Ah, const __nv_bfloat16* __restrict__ Al,
    const __nv_bfloat16* __restrict__ Bh, const __nv_bfloat16* __restrict__ Bl,
    const float* __restrict__ bias, float* __restrict__ C,
    __nv_bfloat16* __restrict__ Ch, __nv_bfloat16* __restrict__ Cl,
    bool splitout, char* sm) {
    const uint32_t sbase = smem_u32(sm);
    float* sbias = (float*)sm;

    const int tid = threadIdx.x;
    const int wid = tid >> 5, lane = tid & 31;
    const int n0 = blockIdx.x * 128, m0 = blockIdx.y * 128;

    if (tid < 128) sbias[tid] = bias[n0 + tid];

    const int wm = (wid & 3) * 32;
    const int wn = (wid >> 2) * 64;

    float acc[2][8][4];
#pragma unroll
    for (int mt = 0; mt < 2; mt++)
#pragma unroll
        for (int nt = 0; nt < 8; nt++)
#pragma unroll
            for (int e = 0; e < 4; e++) acc[mt][nt][e] = 0.f;

    const int cr = tid >> 1;
    const int hcE = (tid & 1) * 16;
    const int localr = lane & 7, sel = lane >> 3;

    const __nv_bfloat16* rowA_h = Ah + (size_t)(m0 + cr) * DD + hcE;
    const __nv_bfloat16* rowA_l = Al + (size_t)(m0 + cr) * DD + hcE;
    const __nv_bfloat16* rowB_h = Bh + (size_t)(n0 + cr) * DD + hcE;
    const __nv_bfloat16* rowB_l = Bl + (size_t)(n0 + cr) * DD + hcE;

#define G_STAGE(c, s)                                                       \
    do {                                                                    \
        const uint32_t stb = sbase + G_ST(s);                               \
        _Pragma("unroll")                                                   \
        for (int j = 0; j < 2; j++) {                                       \
            uint32_t off = SWZ64((uint32_t)(cr * 64 + hcE * 2 + 16 * j));   \
            CPA16(stb + G_AH + off, rowA_h + (size_t)(c) * 32 + 8 * j, 16); \
            CPA16(stb + G_AL + off, rowA_l + (size_t)(c) * 32 + 8 * j, 16); \
            CPA16(stb + G_BH + off, rowB_h + (size_t)(c) * 32 + 8 * j, 16); \
            CPA16(stb + G_BL + off, rowB_l + (size_t)(c) * 32 + 8 * j, 16); \
        }                                                                   \
        CPA_COMMIT();                                                       \
    } while (0)

    G_STAGE(0, 0);
    G_STAGE(1, 1);

    for (int c = 0; c < NCHUNK; c++) {
        const int s = c % 3;
        if (c + 1 < NCHUNK) CPA_WAIT1(); else CPA_WAIT0();
        __syncthreads();
        if (c + 2 < NCHUNK) G_STAGE(c + 2, (c + 2) % 3);

        const uint32_t stb = sbase + G_ST(s);
#pragma unroll
        for (int kk = 0; kk < 32; kk += 16) {
            uint32_t ah[2][4], al[2][4];
#pragma unroll
            for (int mt = 0; mt < 2; mt++) {
                const int row = wm + mt * 16 + localr + (sel & 1) * 8;
                const int kb = kk + (sel >> 1) * 8;
                const uint32_t off = SWZ64((uint32_t)(row * 64 + kb * 2));
                LDSM_X4(ah[mt][0], ah[mt][1], ah[mt][2], ah[mt][3],
                        stb + G_AH + off);
                LDSM_X4(al[mt][0], al[mt][1], al[mt][2], al[mt][3],
                        stb + G_AL + off);
            }
            uint32_t bh[8][2], bl[8][2];
#pragma unroll
            for (int np = 0; np < 4; np++) {
                const int row = wn + np * 16 + (sel >> 1) * 8 + localr;
                const int kb = kk + (sel & 1) * 8;
                const uint32_t off = SWZ64((uint32_t)(row * 64 + kb * 2));
                uint32_t t0, t1, t2, t3;
                LDSM_X4(t0, t1, t2, t3, stb + G_BH + off);
                bh[2 * np][0] = t0; bh[2 * np][1] = t1;
                bh[2 * np + 1][0] = t2; bh[2 * np + 1][1] = t3;
                LDSM_X4(t0, t1, t2, t3, stb + G_BL + off);
                bl[2 * np][0] = t0; bl[2 * np][1] = t1;
                bl[2 * np + 1][0] = t2; bl[2 * np + 1][1] = t3;
            }
            // product-major: 16 independent MMAs per pass, 3 passes
#pragma unroll
            for (int mt = 0; mt < 2; mt++)
#pragma unroll
                for (int nt = 0; nt < 8; nt++)
                    MMA16816(acc[mt][nt], ah[mt], bh[nt]);
#pragma unroll
            for (int mt = 0; mt < 2; mt++)
#pragma unroll
                for (int nt = 0; nt < 8; nt++)
                    MMA16816(acc[mt][nt], ah[mt], bl[nt]);
#pragma unroll
            for (int mt = 0; mt < 2; mt++)
#pragma unroll
                for (int nt = 0; nt < 8; nt++)
                    MMA16816(acc[mt][nt], al[mt], bh[nt]);
        }
    }

    const int er = lane >> 2;
    const int ec = (lane & 3) * 2;
#pragma unroll
    for (int mt = 0; mt < 2; mt++) {
#pragma unroll
        for (int nt = 0; nt < 8; nt++) {
            const int ct = wn + nt * 8 + ec;
            const int row0 = m0 + wm + mt * 16 + er;
            float x0 = acc[mt][nt][0] + sbias[ct];
            float x1 = acc[mt][nt][1] + sbias[ct + 1];
            float x2 = acc[mt][nt][2] + sbias[ct];
            float x3 = acc[mt][nt][3] + sbias[ct + 1];
            const size_t i0 = (size_t)row0 * DD + n0 + ct;
            const size_t i1 = (size_t)(row0 + 8) * DD + n0 + ct;
            if (splitout) {
                uint32_t h0, l0u, h1, l1u;
                split2(x0, x1, h0, l0u);
                split2(x2, x3, h1, l1u);
                *(uint32_t*)&Ch[i0] = h0;
                *(uint32_t*)&Cl[i0] = l0u;
                *(uint32_t*)&Ch[i1] = h1;
                *(uint32_t*)&Cl[i1] = l1u;
            } else {
                float2 v0 = {x0, x1}, v1 = {x2, x3};
                *(float2*)&C[i0] = v0;
                *(float2*)&C[i1] = v1;
            }
        }
    }
#undef G_STAGE
}

// Fused Q/K/V projections: blockIdx.z selects the weight/bias/output triple.
struct QKVArgs {
    const __nv_bfloat16* Bh[3];
    const __nv_bfloat16* Bl[3];
    const float* bias[3];
    __nv_bfloat16* Ch[3];
    __nv_bfloat16* Cl[3];
};

__global__ __launch_bounds__(256, 2)
void gemm_qkv(const __nv_bfloat16* __restrict__ Ah,
              const __nv_bfloat16* __restrict__ Al, QKVArgs a) {
    extern __shared__ char sm[];
    const int w = blockIdx.z;
    gemm_core(Ah, Al, a.Bh[w], a.Bl[w], a.bias[w], nullptr,
              a.Ch[w], a.Cl[w], true, sm);
}

__global__ __launch_bounds__(256, 2)
void gemm_out(const __nv_bfloat16* __restrict__ Ah,
              const __nv_bfloat16* __restrict__ Al,
              const __nv_bfloat16* __restrict__ Bh,
              const __nv_bfloat16* __restrict__ Bl,
              const float* __restrict__ bias, float* __restrict__ C) {
    extern __shared__ char sm[];
    gemm_core(Ah, Al, Bh, Bl, bias, C, nullptr, nullptr, false, sm);
}

// ===========================================================================
// mma.sync sliding-window flash attention, bf16x3, 2-stage cp.async,
// online softmax (exp2 domain), interior-tile mask fast path,
// product-major MMA issue.
// CTA = 128 queries x 1 head, 8 warps (16 q-rows each).
// ===========================================================================
#define A_QH 0
#define A_QL 16384
#define A_ST(s) (32768 + (s) * 32768)
#define A_KH 0
#define A_KL 8192
#define A_VH 16384
#define A_VL 24576
#define ATT_SMEM (32768 + 2 * 32768)
#define SC2 (0.125f * 1.44269504f)   // score scale folded with log2(e)

__global__ __launch_bounds__(256, 2)
void attn_mma(const __nv_bfloat16* __restrict__ Qh,
              const __nv_bfloat16* __restrict__ Ql,
              const __nv_bfloat16* __restrict__ Kh,
              const __nv_bfloat16* __restrict__ Kl,
              const __nv_bfloat16* __restrict__ Vh,
              const __nv_bfloat16* __restrict__ Vl,
              __nv_bfloat16* __restrict__ Oh,
              __nv_bfloat16* __restrict__ Ol) {
    extern __shared__ char sm[];
    const uint32_t sbase = smem_u32(sm);

    const int tid = threadIdx.x;
    const int wid = tid >> 5, lane = tid & 31;
    const int qs = blockIdx.x * 128;
    const int hoff = blockIdx.y * HDIM;
    const int localr = lane & 7, sel = lane >> 3;

    // ---- stage Q tile (128 x 64 bf16 hi/lo), swizzled 128B rows ----
    {
        const int r = tid >> 1;
        const int half = (tid & 1) * 32;
        const size_t g = (size_t)(qs + r) * DD + hoff + half;
#pragma unroll
        for (int j = 0; j < 4; j++) {
            uint32_t off = SWZ((uint32_t)(r * 128 + (half + 8 * j) * 2));
            *(uint4*)(sm + A_QH + off) = *(const uint4*)&Qh[g + 8 * j];
            *(uint4*)(sm + A_QL + off) = *(const uint4*)&Ql[g + 8 * j];
        }
    }

    const int t0v = max(0, (512 - qs + 63) / 64);
    const int t1v = min(18, (SS + 512 - qs) / 64);

    const int svr = tid >> 2;
    const int svc = (tid & 3) * 16;

#define A_STAGE(t, s)                                                       \
    do {                                                                    \
        const int kabs_ = qs - 512 + 64 * (t) + svr;                        \
        const size_t g_ = (size_t)kabs_ * DD + hoff + svc;                  \
        const uint32_t stb_ = sbase + A_ST(s);                              \
        _Pragma("unroll")                                                   \
        for (int j = 0; j < 2; j++) {                                       \
            uint32_t off = SWZ((uint32_t)(svr * 128 + (svc + 8 * j) * 2));  \
            CPA16(stb_ + A_KH + off, &Kh[g_ + 8 * j], 16u);                 \
            CPA16(stb_ + A_KL + off, &Kl[g_ + 8 * j], 16u);                 \
            CPA16(stb_ + A_VH + off, &Vh[g_ + 8 * j], 16u);                 \
            CPA16(stb_ + A_VL + off, &Vl[g_ + 8 * j], 16u);                 \
        }                                                                   \
        CPA_COMMIT();                                                       \
    } while (0)

    const int q0 = qs + 16 * wid + (lane >> 2);
    const int q1 = q0 + 8;

    float m0 = -1e30f, m1 = -1e30f, l0 = 0.f, l1 = 0.f;
    float oacc[8][4];
#pragma unroll
    for (int nt = 0; nt < 8; nt++)
#pragma unroll
        for (int e = 0; e < 4; e++) oacc[nt][e] = 0.f;

    A_STAGE(t0v, 0);

    for (int t = t0v; t < t1v; t++) {
        const int s = (t - t0v) & 1;
        const int kt = qs - 512 + 64 * t;
        CPA_WAIT0();
        __syncthreads();
        if (t + 1 < t1v) A_STAGE(t + 1, s ^ 1);

        const uint32_t stb = sbase + A_ST(s);

        // ---- QK^T: S (16q x 64k per warp), product-major MMAs ----
        float sacc[8][4];
#pragma unroll
        for (int nt = 0; nt < 8; nt++)
#pragma unroll
            for (int e = 0; e < 4; e++) sacc[nt][e] = 0.f;

#pragma unroll
        for (int kk = 0; kk < 64; kk += 16) {
            uint32_t qhf[4], qlf[4];
            {
                const int row = 16 * wid + localr + (sel & 1) * 8;
                const int kb = kk + (sel >> 1) * 8;
                const uint32_t off = SWZ((uint32_t)(row * 128 + kb * 2));
                LDSM_X4(qhf[0], qhf[1], qhf[2], qhf[3], sbase + A_QH + off);
                LDSM_X4(qlf[0], qlf[1], qlf[2], qlf[3], sbase + A_QL + off);
            }
            uint32_t khf[8][2], klf[8][2];
#pragma unroll
            for (int np = 0; np < 4; np++) {
                const int row = np * 16 + (sel >> 1) * 8 + localr;
                const int kb = kk + (sel & 1) * 8;
                const uint32_t off = SWZ((uint32_t)(row * 128 + kb * 2));
                uint32_t t0r, t1r, t2r, t3r;
                LDSM_X4(t0r, t1r, t2r, t3r, stb + A_KH + off);
                khf[2 * np][0] = t0r; khf[2 * np][1] = t1r;
                khf[2 * np + 1][0] = t2r; khf[2 * np + 1][1] = t3r;
                LDSM_X4(t0r, t1r, t2r, t3r, stb + A_KL + off);
                klf[2 * np][0] = t0r; klf[2 * np][1] = t1r;
                klf[2 * np + 1][0] = t2r; klf[2 * np + 1][1] = t3r;
            }
#pragma unroll
            for (int nt = 0; nt < 8; nt++)
                MMA16816(sacc[nt], qhf, khf[nt]);
#pragma unroll
            for (int nt = 0; nt < 8; nt++)
                MMA16816(sacc[nt], qhf, klf[nt]);
#pragma unroll
            for (int nt = 0; nt < 8; nt++)
                MMA16816(sacc[nt], qlf, khf[nt]);
        }

        // ---- scale to exp2 domain (+ window mask on edge tiles) + max ----
        float mx0 = -1e30f, mx1 = -1e30f;
        if (t < 2 || t > 15) {
            const int cb = kt + 2 * (lane & 3);
#pragma unroll
            for (int nt = 0; nt < 8; nt++) {
#pragma unroll
                for (int e = 0; e < 2; e++) {
                    const int kabs = cb + 8 * nt + e;
                    float s0 = ((kabs >= q0 - 512) & (kabs < q0 + 512))
                                   ? sacc[nt][e] * SC2 : -1e30f;
                    float s1 = ((kabs >= q1 - 512) & (kabs < q1 + 512))
                                   ? sacc[nt][e + 2] * SC2 : -1e30f;
                    sacc[nt][e] = s0; sacc[nt][e + 2] = s1;
                    mx0 = fmaxf(mx0, s0); mx1 = fmaxf(mx1, s1);
                }
            }
        } else {
#pragma unroll
            for (int nt = 0; nt < 8; nt++) {
#pragma unroll
                for (int e = 0; e < 2; e++) {
                    float s0 = sacc[nt][e] * SC2;
                    float s1 = sacc[nt][e + 2] * SC2;
                    sacc[nt][e] = s0; sacc[nt][e + 2] = s1;
                    mx0 = fmaxf(mx0, s0); mx1 = fmaxf(mx1, s1);
                }
            }
        }
        mx0 = fmaxf(mx0, __shfl_xor_sync(0xffffffffu, mx0, 1));
        mx0 = fmaxf(mx0, __shfl_xor_sync(0xffffffffu, mx0, 2));
        mx1 = fmaxf(mx1, __shfl_xor_sync(0xffffffffu, mx1, 1));
        mx1 = fmaxf(mx1, __shfl_xor_sync(0xffffffffu, mx1, 2));
        const float mn0 = fmaxf(m0, mx0), mn1 = fmaxf(m1, mx1);
        const float a0 = exp2f(m0 - mn0), a1 = exp2f(m1 - mn1);
        m0 = mn0; m1 = mn1;
        float rs0 = 0.f, rs1 = 0.f;
#pragma unroll
        for (int nt = 0; nt < 8; nt++) {
#pragma unroll
            for (int e = 0; e < 2; e++) {
                float p0 = (sacc[nt][e] > -5e29f) ? exp2f(sacc[nt][e] - mn0) : 0.f;
                float p1 = (sacc[nt][e + 2] > -5e29f) ? exp2f(sacc[nt][e + 2] - mn1) : 0.f;
                rs0 += p0; rs1 += p1;
                sacc[nt][e] = p0; sacc[nt][e + 2] = p1;
            }
        }
        l0 = l0 * a0 + rs0;
        l1 = l1 * a1 + rs1;
#pragma unroll
        for (int nt = 0; nt < 8; nt++) {
            oacc[nt][0] *= a0; oacc[nt][1] *= a0;
            oacc[nt][2] *= a1; oacc[nt][3] *= a1;
        }

        // ---- PV: O += P * V, product-major MMAs ----
#pragma unroll
        for (int kc = 0; kc < 4; kc++) {
            uint32_t pah[4], pal[4];
            split2(sacc[2 * kc][0], sacc[2 * kc][1], pah[0], pal[0]);
            split2(sacc[2 * kc][2], sacc[2 * kc][3], pah[1], pal[1]);
            split2(sacc[2 * kc + 1][0], sacc[2 * kc + 1][1], pah[2], pal[2]);
            split2(sacc[2 * kc + 1][2], sacc[2 * kc + 1][3], pah[3], pal[3]);

            uint32_t vhf[8][2], vlf[8][2];
#pragma unroll
            for (int ntp = 0; ntp < 4; ntp++) {
                const int key = 16 * kc + (sel & 1) * 8 + localr;
                const int dim = (2 * ntp + (sel >> 1)) * 8;
                const uint32_t off = SWZ((uint32_t)(key * 128 + dim * 2));
                uint32_t t0r, t1r, t2r, t3r;
                LDSM_X4_T(t0r, t1r, t2r, t3r, stb + A_VH + off);
                vhf[2 * ntp][0] = t0r; vhf[2 * ntp][1] = t1r;
                vhf[2 * ntp + 1][0] = t2r; vhf[2 * ntp + 1][1] = t3r;
                LDSM_X4_T(t0r, t1r, t2r, t3r, stb + A_VL + off);
                vlf[2 * ntp][0] = t0r; vlf[2 * ntp][1] = t1r;
                vlf[2 * ntp + 1][0] = t2r; vlf[2 * ntp + 1][1] = t3r;
            }
#pragma unroll
            for (int nt = 0; nt < 8; nt++)
                MMA16816(oacc[nt], pah, vhf[nt]);
#pragma unroll
            for (int nt = 0; nt < 8; nt++)
                MMA16816(oacc[nt], pah, vlf[nt]);
#pragma unroll
            for (int nt = 0; nt < 8; nt++)
                MMA16816(oacc[nt], pal, vhf[nt]);
        }
    }

    // ---- epilogue: normalize, blend weight, write bf16 hi/lo ----
    l0 += __shfl_xor_sync(0xffffffffu, l0, 1);
    l0 += __shfl_xor_sync(0xffffffffu, l0, 2);
    l1 += __shfl_xor_sync(0xffffffffu, l1, 1);
    l1 += __shfl_xor_sync(0xffffffffu, l1, 2);
    float w0 = 1.f, w1 = 1.f;
    if (q0 >= SS - 128) w0 = 1.f + (float)(q0 - (SS - 128)) * (1.f / 127.f);
    if (q1 >= SS - 128) w1 = 1.f + (float)(q1 - (SS - 128)) * (1.f / 127.f);
    const float sc0 = w0 / l0, sc1 = w1 / l1;
    const int ec = 2 * (lane & 3);
#pragma unroll
    for (int nt = 0; nt < 8; nt++) {
        const size_t i0 = (size_t)q0 * DD + hoff + 8 * nt + ec;
        const size_t i1 = (size_t)q1 * DD + hoff + 8 * nt + ec;
        uint32_t h0, l0u, h1, l1u;
        split2(oacc[nt][0] * sc0, oacc[nt][1] * sc0, h0, l0u);
        split2(oacc[nt][2] * sc1, oacc[nt][3] * sc1, h1, l1u);
        *(uint32_t*)&Oh[i0] = h0;
        *(uint32_t*)&Ol[i0] = l0u;
        *(uint32_t*)&Oh[i1] = h1;
        *(uint32_t*)&Ol[i1] = l1u;
    }
}

// ===========================================================================
extern "C" void kernel_launch(void* const* d_in, const int* in_sizes, int n_in,
                              void* d_out, int out_size) {
    const float* x = nullptr;
    const float* Wm[4] = {nullptr, nullptr, nullptr, nullptr};
    const float* bm[4] = {nullptr, nullptr, nullptr, nullptr};
    int nw = 0, nb = 0;
    for (int i = 0; i < n_in; i++) {
        const float* p = (const float*)d_in[i];
        if (in_sizes[i] == SS * DD) x = p;
        else if (in_sizes[i] == DD * DD) { if (nw < 4) Wm[nw++] = p; }
        else if (in_sizes[i] == DD) { if (nb < 4) bm[nb++] = p; }
    }
    float* out = (float*)d_out;

    __nv_bfloat16 *xh, *xl, *Wh, *Wl, *Qh, *Ql, *Kh, *Kl, *Vh, *Vl, *Oh, *Ol;
    cudaGetSymbolAddress((void**)&xh, g_xh);
    cudaGetSymbolAddress((void**)&xl, g_xl);
    cudaGetSymbolAddress((void**)&Wh, g_Wh);
    cudaGetSymbolAddress((void**)&Wl, g_Wl);
    cudaGetSymbolAddress((void**)&Qh, g_Qh);
    cudaGetSymbolAddress((void**)&Ql, g_Ql);
    cudaGetSymbolAddress((void**)&Kh, g_Kh);
    cudaGetSymbolAddress((void**)&Kl, g_Kl);
    cudaGetSymbolAddress((void**)&Vh, g_Vh);
    cudaGetSymbolAddress((void**)&Vl, g_Vl);
    cudaGetSymbolAddress((void**)&Oh, g_Oh);
    cudaGetSymbolAddress((void**)&Ol, g_Ol);

    // ---- fused split of x and all 4 weights (one launch) ----
    const int NTOT = NX8 + 4 * NW8;
    split_all<<<(NTOT + 255) / 256, 256>>>(x, Wm[0], Wm[1], Wm[2], Wm[3],
                                           xh, xl, Wh, Wl);

    cudaFuncSetAttribute(gemm_qkv, cudaFuncAttributeMaxDynamicSharedMemorySize,
                         GEMM_SMEM);
    cudaFuncSetAttribute(gemm_out, cudaFuncAttributeMaxDynamicSharedMemorySize,
                         GEMM_SMEM);
    cudaFuncSetAttribute(attn_mma, cudaFuncAttributeMaxDynamicSharedMemorySize,
                         ATT_SMEM);

    // ---- fused Q/K/V projections ----
    QKVArgs qa;
    qa.Bh[0] = Wh;                       qa.Bl[0] = Wl;
    qa.Bh[1] = Wh + (size_t)1 * DD * DD; qa.Bl[1] = Wl + (size_t)1 * DD * DD;
    qa.Bh[2] = Wh + (size_t)2 * DD * DD; qa.Bl[2] = Wl + (size_t)2 * DD * DD;
    qa.bias[0] = bm[0]; qa.bias[1] = bm[1]; qa.bias[2] = bm[2];
    qa.Ch[0] = Qh; qa.Cl[0] = Ql;
    qa.Ch[1] = Kh; qa.Cl[1] = Kl;
    qa.Ch[2] = Vh; qa.Cl[2] = Vl;

    dim3 qkvgrid(DD / 128, SS / 128, 3);
    gemm_qkv<<<qkvgrid, 256, GEMM_SMEM>>>(xh, xl, qa);

    attn_mma<<<dim3(SS / 128, HH), 256, ATT_SMEM>>>(Qh, Ql, Kh, Kl, Vh, Vl,
                                                    Oh, Ol);

    dim3 ogrid(DD / 128, SS / 128);
    gemm_out<<<ogrid, 256, GEMM_SMEM>>>(Oh, Ol, Wh + (size_t)3 * DD * DD,
                                        Wl + (size_t)3 * DD * DD, bm[3], out);
}

// round 13
// speedup vs baseline: 1.0176x; 1.0023x over previous
#include <cuda_runtime.h>
#include <cuda_bf16.h>
#include <stdint.h>
#include <math.h>

#define SS 8192
#define DD 1024
#define HH 16
#define HDIM 64

// ---- scratch: bf16 hi/lo pairs (static device arrays) ----
__device__ __nv_bfloat16 g_xh[SS * DD], g_xl[SS * DD];
__device__ __nv_bfloat16 g_Wh[4][DD * DD], g_Wl[4][DD * DD];
__device__ __nv_bfloat16 g_Qh[SS * DD], g_Ql[SS * DD];
__device__ __nv_bfloat16 g_Kh[SS * DD], g_Kl[SS * DD];
__device__ __nv_bfloat16 g_Vh[SS * DD], g_Vl[SS * DD];
__device__ __nv_bfloat16 g_Oh[SS * DD], g_Ol[SS * DD];

// ===========================================================================
// PTX helpers (baseline ISA: ldmatrix + mma.sync + cp.async, sm_80+)
// ===========================================================================
__device__ __forceinline__ uint32_t smem_u32(const void* p) {
    uint32_t a;
    asm("{ .reg .u64 t; cvta.to.shared.u64 t, %1; cvt.u32.u64 %0, t; }"
        : "=r"(a) : "l"(p));
    return a;
}

#define LDSM_X4(r0, r1, r2, r3, addr)                                       \
    asm volatile(                                                           \
        "ldmatrix.sync.aligned.m8n8.x4.shared.b16 {%0, %1, %2, %3}, [%4];"  \
        : "=r"(r0), "=r"(r1), "=r"(r2), "=r"(r3) : "r"(addr))

#define LDSM_X4_T(r0, r1, r2, r3, addr)                                     \
    asm volatile(                                                           \
        "ldmatrix.sync.aligned.m8n8.x4.trans.shared.b16 {%0, %1, %2, %3}, [%4];" \
        : "=r"(r0), "=r"(r1), "=r"(r2), "=r"(r3) : "r"(addr))

#define MMA16816(d, a, b)                                                   \
    asm volatile(                                                           \
        "mma.sync.aligned.m16n8k16.row.col.f32.bf16.bf16.f32 "              \
        "{%0, %1, %2, %3}, {%4, %5, %6, %7}, {%8, %9}, {%0, %1, %2, %3};"   \
        : "+f"((d)[0]), "+f"((d)[1]), "+f"((d)[2]), "+f"((d)[3])            \
        : "r"((a)[0]), "r"((a)[1]), "r"((a)[2]), "r"((a)[3]),               \
          "r"((b)[0]), "r"((b)[1]))

#define CPA16(dst, src, sz)                                                 \
    asm volatile("cp.async.cg.shared.global [%0], [%1], 16, %2;"            \
                 :: "r"(dst), "l"(src), "r"(sz))
#define CPA_COMMIT() asm volatile("cp.async.commit_group;" ::: "memory")
#define CPA_WAIT1()  asm volatile("cp.async.wait_group 1;" ::: "memory")
#define CPA_WAIT0()  asm volatile("cp.async.wait_group 0;" ::: "memory")

#define SWZ(o)   ((o) ^ (((o) >> 3) & 0x70))   // 128B rows
#define SWZ64(o) ((o) ^ (((o) >> 3) & 0x30))   // 64B rows

// Single-instruction bf16x2 pack: {lo=x, hi=y}, round-to-nearest.
__device__ __forceinline__ uint32_t packbf(float x, float y) {
    uint32_t r;
    asm("cvt.rn.bf16x2.f32 %0, %1, %2;" : "=r"(r) : "f"(y), "f"(x));
    return r;
}
// hi/lo split of a float pair: h = bf16x2(x,y); l = bf16x2 of residues.
__device__ __forceinline__ void split2(float x, float y,
                                       uint32_t& h, uint32_t& l) {
    h = packbf(x, y);
    float hx = __uint_as_float(h << 16);
    float hy = __uint_as_float(h & 0xffff0000u);
    l = packbf(x - hx, y - hy);
}

// ===========================================================================
// Fused fp32 -> bf16 hi/lo split for x + the 4 weight matrices (one launch).
// ===========================================================================
#define NX8 (SS * DD / 8)
#define NW8 (DD * DD / 8)

__global__ void split_all(const float* __restrict__ x,
                          const float* __restrict__ w0,
                          const float* __restrict__ w1,
                          const float* __restrict__ w2,
                          const float* __restrict__ w3,
                          __nv_bfloat16* __restrict__ xh,
                          __nv_bfloat16* __restrict__ xl,
                          __nv_bfloat16* __restrict__ Wh,
                          __nv_bfloat16* __restrict__ Wl) {
    int idx = blockIdx.x * blockDim.x + threadIdx.x;
    if (idx >= NX8 + 4 * NW8) return;
    const float* src;
    __nv_bfloat16 *dh, *dl;
    size_t off;
    if (idx < NX8) {
        src = x; dh = xh; dl = xl; off = idx;
    } else {
        int r = idx - NX8;
        int w = r >> 17;           // / NW8 (2^17)
        int o = r & (NW8 - 1);
        const float* ws[4] = {w0, w1, w2, w3};
        src = ws[w];
        dh = Wh + (size_t)w * DD * DD;
        dl = Wl + (size_t)w * DD * DD;
        off = o;
    }
    const float4* p = (const float4*)src + off * 2;
    float4 v0 = p[0], v1 = p[1];
    uint32_t h[4], l[4];
    split2(v0.x, v0.y, h[0], l[0]);
    split2(v0.z, v0.w, h[1], l[1]);
    split2(v1.x, v1.y, h[2], l[2]);
    split2(v1.z, v1.w, h[3], l[3]);
    ((uint4*)dh)[off] = *(uint4*)h;
    ((uint4*)dl)[off] = *(uint4*)l;
}

// ===========================================================================
// Shared GEMM core: mma.sync, bf16x3 emulated-fp32, 3-stage cp.async, occ 2.
//   C[m,n] = sum_k A[m,k]*W[n,k] + bias[n]
// CTA 128x128, K-chunk 32 (64B rows, SW64), 256 threads (8 warps 32m x 64n).
// MMAs issued PRODUCT-MAJOR: consecutive MMAs never share an accumulator,
// so HMMA RAW chains are fully pipelined at 4 warps/SMSP.
// ===========================================================================
#define G_ST(s)  (1024 + (s) * 32768)
#define G_AH 0
#define G_AL 8192
#define G_BH 16384
#define G_BL 24576
#define GEMM_SMEM (1024 + 3 * 32768)
#define NCHUNK 32

__device__ __forceinline__ void gemm_core(
    const __nv_bfloat16* __restrict__ Ah, const __nv_bfloat16* __restrict__ Al,
    const __nv_bfloat16* __restrict__ Bh, const __nv_bfloat16* __restrict__ Bl,
    const float* __restrict__ bias, float* __restrict__ C,
    __nv_bfloat16* __restrict__ Ch, __nv_bfloat16* __restrict__ Cl,
    bool splitout, char* sm) {
    const uint32_t sbase = smem_u32(sm);
    float* sbias = (float*)sm;

    const int tid = threadIdx.x;
    const int wid = tid >> 5, lane = tid & 31;
    const int n0 = blockIdx.x * 128, m0 = blockIdx.y * 128;

    if (tid < 128) sbias[tid] = bias[n0 + tid];

    const int wm = (wid & 3) * 32;
    const int wn = (wid >> 2) * 64;

    float acc[2][8][4];
#pragma unroll
    for (int mt = 0; mt < 2; mt++)
#pragma unroll
        for (int nt = 0; nt < 8; nt++)
#pragma unroll
            for (int e = 0; e < 4; e++) acc[mt][nt][e] = 0.f;

    const int cr = tid >> 1;
    const int hcE = (tid & 1) * 16;
    const int localr = lane & 7, sel = lane >> 3;

    const __nv_bfloat16* rowA_h = Ah + (size_t)(m0 + cr) * DD + hcE;
    const __nv_bfloat16* rowA_l = Al + (size_t)(m0 + cr) * DD + hcE;
    const __nv_bfloat16* rowB_h = Bh + (size_t)(n0 + cr) * DD + hcE;
    const __nv_bfloat16* rowB_l = Bl + (size_t)(n0 + cr) * DD + hcE;

#define G_STAGE(c, s)                                                       \
    do {                                                                    \
        const uint32_t stb = sbase + G_ST(s);                               \
        _Pragma("unroll")                                                   \
        for (int j = 0; j < 2; j++) {                                       \
            uint32_t off = SWZ64((uint32_t)(cr * 64 + hcE * 2 + 16 * j));   \
            CPA16(stb + G_AH + off, rowA_h + (size_t)(c) * 32 + 8 * j, 16); \
            CPA16(stb + G_AL + off, rowA_l + (size_t)(c) * 32 + 8 * j, 16); \
            CPA16(stb + G_BH + off, rowB_h + (size_t)(c) * 32 + 8 * j, 16); \
            CPA16(stb + G_BL + off, rowB_l + (size_t)(c) * 32 + 8 * j, 16); \
        }                                                                   \
        CPA_COMMIT();                                                       \
    } while (0)

    G_STAGE(0, 0);
    G_STAGE(1, 1);

    for (int c = 0; c < NCHUNK; c++) {
        const int s = c % 3;
        if (c + 1 < NCHUNK) CPA_WAIT1(); else CPA_WAIT0();
        __syncthreads();
        if (c + 2 < NCHUNK) G_STAGE(c + 2, (c + 2) % 3);

        const uint32_t stb = sbase + G_ST(s);
#pragma unroll
        for (int kk = 0; kk < 32; kk += 16) {
            uint32_t ah[2][4], al[2][4];
#pragma unroll
            for (int mt = 0; mt < 2; mt++) {
                const int row = wm + mt * 16 + localr + (sel & 1) * 8;
                const int kb = kk + (sel >> 1) * 8;
                const uint32_t off = SWZ64((uint32_t)(row * 64 + kb * 2));
                LDSM_X4(ah[mt][0], ah[mt][1], ah[mt][2], ah[mt][3],
                        stb + G_AH + off);
                LDSM_X4(al[mt][0], al[mt][1], al[mt][2], al[mt][3],
                        stb + G_AL + off);
            }
            uint32_t bh[8][2], bl[8][2];
#pragma unroll
            for (int np = 0; np < 4; np++) {
                const int row = wn + np * 16 + (sel >> 1) * 8 + localr;
                const int kb = kk + (sel & 1) * 8;
                const uint32_t off = SWZ64((uint32_t)(row * 64 + kb * 2));
                uint32_t t0, t1, t2, t3;
                LDSM_X4(t0, t1, t2, t3, stb + G_BH + off);
                bh[2 * np][0] = t0; bh[2 * np][1] = t1;
                bh[2 * np + 1][0] = t2; bh[2 * np + 1][1] = t3;
                LDSM_X4(t0, t1, t2, t3, stb + G_BL + off);
                bl[2 * np][0] = t0; bl[2 * np][1] = t1;
                bl[2 * np + 1][0] = t2; bl[2 * np + 1][1] = t3;
            }
            // product-major: 16 independent MMAs per pass, 3 passes
#pragma unroll
            for (int mt = 0; mt < 2; mt++)
#pragma unroll
                for (int nt = 0; nt < 8; nt++)
                    MMA16816(acc[mt][nt], ah[mt], bh[nt]);
#pragma unroll
            for (int mt = 0; mt < 2; mt++)
#pragma unroll
                for (int nt = 0; nt < 8; nt++)
                    MMA16816(acc[mt][nt], ah[mt], bl[nt]);
#pragma unroll
            for (int mt = 0; mt < 2; mt++)
#pragma unroll
                for (int nt = 0; nt < 8; nt++)
                    MMA16816(acc[mt][nt], al[mt], bh[nt]);
        }
    }

    const int er = lane >> 2;
    const int ec = (lane & 3) * 2;
#pragma unroll
    for (int mt = 0; mt < 2; mt++) {
#pragma unroll
        for (int nt = 0; nt < 8; nt++) {
            const int ct = wn + nt * 8 + ec;
            const int row0 = m0 + wm + mt * 16 + er;
            float x0 = acc[mt][nt][0] + sbias[ct];
            float x1 = acc[mt][nt][1] + sbias[ct + 1];
            float x2 = acc[mt][nt][2] + sbias[ct];
            float x3 = acc[mt][nt][3] + sbias[ct + 1];
            const size_t i0 = (size_t)row0 * DD + n0 + ct;
            const size_t i1 = (size_t)(row0 + 8) * DD + n0 + ct;
            if (splitout) {
                uint32_t h0, l0u, h1, l1u;
                split2(x0, x1, h0, l0u);
                split2(x2, x3, h1, l1u);
                *(uint32_t*)&Ch[i0] = h0;
                *(uint32_t*)&Cl[i0] = l0u;
                *(uint32_t*)&Ch[i1] = h1;
                *(uint32_t*)&Cl[i1] = l1u;
            } else {
                float2 v0 = {x0, x1}, v1 = {x2, x3};
                *(float2*)&C[i0] = v0;
                *(float2*)&C[i1] = v1;
            }
        }
    }
#undef G_STAGE
}

// Fused Q/K/V projections: blockIdx.z selects the weight/bias/output triple.
struct QKVArgs {
    const __nv_bfloat16* Bh[3];
    const __nv_bfloat16* Bl[3];
    const float* bias[3];
    __nv_bfloat16* Ch[3];
    __nv_bfloat16* Cl[3];
};

__global__ __launch_bounds__(256, 2)
void gemm_qkv(const __nv_bfloat16* __restrict__ Ah,
              const __nv_bfloat16* __restrict__ Al, QKVArgs a) {
    extern __shared__ char sm[];
    const int w = blockIdx.z;
    gemm_core(Ah, Al, a.Bh[w], a.Bl[w], a.bias[w], nullptr,
              a.Ch[w], a.Cl[w], true, sm);
}

__global__ __launch_bounds__(256, 2)
void gemm_out(const __nv_bfloat16* __restrict__ Ah,
              const __nv_bfloat16* __restrict__ Al,
              const __nv_bfloat16* __restrict__ Bh,
              const __nv_bfloat16* __restrict__ Bl,
              const float* __restrict__ bias, float* __restrict__ C) {
    extern __shared__ char sm[];
    gemm_core(Ah, Al, Bh, Bl, bias, C, nullptr, nullptr, false, sm);
}

// ===========================================================================
// mma.sync sliding-window flash attention, bf16x3, 2-stage cp.async,
// online softmax (exp2 domain), interior-tile mask fast path,
// product-major MMA issue.
// CTA = 128 queries x 1 head, 8 warps (16 q-rows each).
// ===========================================================================
#define A_QH 0
#define A_QL 16384
#define A_ST(s) (32768 + (s) * 32768)
#define A_KH 0
#define A_KL 8192
#define A_VH 16384
#define A_VL 24576
#define ATT_SMEM (32768 + 2 * 32768)
#define SC2 (0.125f * 1.44269504f)   // score scale folded with log2(e)

__global__ __launch_bounds__(256, 2)
void attn_mma(const __nv_bfloat16* __restrict__ Qh,
              const __nv_bfloat16* __restrict__ Ql,
              const __nv_bfloat16* __restrict__ Kh,
              const __nv_bfloat16* __restrict__ Kl,
              const __nv_bfloat16* __restrict__ Vh,
              const __nv_bfloat16* __restrict__ Vl,
              __nv_bfloat16* __restrict__ Oh,
              __nv_bfloat16* __restrict__ Ol) {
    extern __shared__ char sm[];
    const uint32_t sbase = smem_u32(sm);

    const int tid = threadIdx.x;
    const int wid = tid >> 5, lane = tid & 31;
    const int qs = blockIdx.x * 128;
    const int hoff = blockIdx.y * HDIM;
    const int localr = lane & 7, sel = lane >> 3;

    // ---- stage Q tile (128 x 64 bf16 hi/lo), swizzled 128B rows ----
    {
        const int r = tid >> 1;
        const int half = (tid & 1) * 32;
        const size_t g = (size_t)(qs + r) * DD + hoff + half;
#pragma unroll
        for (int j = 0; j < 4; j++) {
            uint32_t off = SWZ((uint32_t)(r * 128 + (half + 8 * j) * 2));
            *(uint4*)(sm + A_QH + off) = *(const uint4*)&Qh[g + 8 * j];
            *(uint4*)(sm + A_QL + off) = *(const uint4*)&Ql[g + 8 * j];
        }
    }

    const int t0v = max(0, (512 - qs + 63) / 64);
    const int t1v = min(18, (SS + 512 - qs) / 64);

    const int svr = tid >> 2;
    const int svc = (tid & 3) * 16;

#define A_STAGE(t, s)                                                       \
    do {                                                                    \
        const int kabs_ = qs - 512 + 64 * (t) + svr;                        \
        const size_t g_ = (size_t)kabs_ * DD + hoff + svc;                  \
        const uint32_t stb_ = sbase + A_ST(s);                              \
        _Pragma("unroll")                                                   \
        for (int j = 0; j < 2; j++) {                                       \
            uint32_t off = SWZ((uint32_t)(svr * 128 + (svc + 8 * j) * 2));  \
            CPA16(stb_ + A_KH + off, &Kh[g_ + 8 * j], 16u);                 \
            CPA16(stb_ + A_KL + off, &Kl[g_ + 8 * j], 16u);                 \
            CPA16(stb_ + A_VH + off, &Vh[g_ + 8 * j], 16u);                 \
            CPA16(stb_ + A_VL + off, &Vl[g_ + 8 * j], 16u);                 \
        }                                                                   \
        CPA_COMMIT();                                                       \
    } while (0)

    const int q0 = qs + 16 * wid + (lane >> 2);
    const int q1 = q0 + 8;

    float m0 = -1e30f, m1 = -1e30f, l0 = 0.f, l1 = 0.f;
    float oacc[8][4];
#pragma unroll
    for (int nt = 0; nt < 8; nt++)
#pragma unroll
        for (int e = 0; e < 4; e++) oacc[nt][e] = 0.f;

    A_STAGE(t0v, 0);

    for (int t = t0v; t < t1v; t++) {
        const int s = (t - t0v) & 1;
        const int kt = qs - 512 + 64 * t;
        CPA_WAIT0();
        __syncthreads();
        if (t + 1 < t1v) A_STAGE(t + 1, s ^ 1);

        const uint32_t stb = sbase + A_ST(s);

        // ---- QK^T: S (16q x 64k per warp), product-major MMAs ----
        float sacc[8][4];
#pragma unroll
        for (int nt = 0; nt < 8; nt++)
#pragma unroll
            for (int e = 0; e < 4; e++) sacc[nt][e] = 0.f;

#pragma unroll
        for (int kk = 0; kk < 64; kk += 16) {
            uint32_t qhf[4], qlf[4];
            {
                const int row = 16 * wid + localr + (sel & 1) * 8;
                const int kb = kk + (sel >> 1) * 8;
                const uint32_t off = SWZ((uint32_t)(row * 128 + kb * 2));
                LDSM_X4(qhf[0], qhf[1], qhf[2], qhf[3], sbase + A_QH + off);
                LDSM_X4(qlf[0], qlf[1], qlf[2], qlf[3], sbase + A_QL + off);
            }
            uint32_t khf[8][2], klf[8][2];
#pragma unroll
            for (int np = 0; np < 4; np++) {
                const int row = np * 16 + (sel >> 1) * 8 + localr;
                const int kb = kk + (sel & 1) * 8;
                const uint32_t off = SWZ((uint32_t)(row * 128 + kb * 2));
                uint32_t t0r, t1r, t2r, t3r;
                LDSM_X4(t0r, t1r, t2r, t3r, stb + A_KH + off);
                khf[2 * np][0] = t0r; khf[2 * np][1] = t1r;
                khf[2 * np + 1][0] = t2r; khf[2 * np + 1][1] = t3r;
                LDSM_X4(t0r, t1r, t2r, t3r, stb + A_KL + off);
                klf[2 * np][0] = t0r; klf[2 * np][1] = t1r;
                klf[2 * np + 1][0] = t2r; klf[2 * np + 1][1] = t3r;
            }
#pragma unroll
            for (int nt = 0; nt < 8; nt++)
                MMA16816(sacc[nt], qhf, khf[nt]);
#pragma unroll
            for (int nt = 0; nt < 8; nt++)
                MMA16816(sacc[nt], qhf, klf[nt]);
#pragma unroll
            for (int nt = 0; nt < 8; nt++)
                MMA16816(sacc[nt], qlf, khf[nt]);
        }

        // ---- scale to exp2 domain (+ window mask on edge tiles) + max ----
        float mx0 = -1e30f, mx1 = -1e30f;
        if (t < 2 || t > 15) {
            const int cb = kt + 2 * (lane & 3);
#pragma unroll
            for (int nt = 0; nt < 8; nt++) {
#pragma unroll
                for (int e = 0; e < 2; e++) {
                    const int kabs = cb + 8 * nt + e;
                    float s0 = ((kabs >= q0 - 512) & (kabs < q0 + 512))
                                   ? sacc[nt][e] * SC2 : -1e30f;
                    float s1 = ((kabs >= q1 - 512) & (kabs < q1 + 512))
                                   ? sacc[nt][e + 2] * SC2 : -1e30f;
                    sacc[nt][e] = s0; sacc[nt][e + 2] = s1;
                    mx0 = fmaxf(mx0, s0); mx1 = fmaxf(mx1, s1);
                }
            }
        } else {
#pragma unroll
            for (int nt = 0; nt < 8; nt++) {
#pragma unroll
                for (int e = 0; e < 2; e++) {
                    float s0 = sacc[nt][e] * SC2;
                    float s1 = sacc[nt][e + 2] * SC2;
                    sacc[nt][e] = s0; sacc[nt][e + 2] = s1;
                    mx0 = fmaxf(mx0, s0); mx1 = fmaxf(mx1, s1);
                }
            }
        }
        mx0 = fmaxf(mx0, __shfl_xor_sync(0xffffffffu, mx0, 1));
        mx0 = fmaxf(mx0, __shfl_xor_sync(0xffffffffu, mx0, 2));
        mx1 = fmaxf(mx1, __shfl_xor_sync(0xffffffffu, mx1, 1));
        mx1 = fmaxf(mx1, __shfl_xor_sync(0xffffffffu, mx1, 2));
        const float mn0 = fmaxf(m0, mx0), mn1 = fmaxf(m1, mx1);
        const float a0 = exp2f(m0 - mn0), a1 = exp2f(m1 - mn1);
        m0 = mn0; m1 = mn1;
        float rs0 = 0.f, rs1 = 0.f;
#pragma unroll
        for (int nt = 0; nt < 8; nt++) {
#pragma unroll
            for (int e = 0; e < 2; e++) {
                float p0 = (sacc[nt][e] > -5e29f) ? exp2f(sacc[nt][e] - mn0) : 0.f;
                float p1 = (sacc[nt][e + 2] > -5e29f) ? exp2f(sacc[nt][e + 2] - mn1) : 0.f;
                rs0 += p0; rs1 += p1;
                sacc[nt][e] = p0; sacc[nt][e + 2] = p1;
            }
        }
        l0 = l0 * a0 + rs0;
        l1 = l1 * a1 + rs1;
#pragma unroll
        for (int nt = 0; nt < 8; nt++) {
            oacc[nt][0] *= a0; oacc[nt][1] *= a0;
            oacc[nt][2] *= a1; oacc[nt][3] *= a1;
        }

        // ---- PV: O += P * V, product-major MMAs ----
#pragma unroll
        for (int kc = 0; kc < 4; kc++) {
            uint32_t pah[4], pal[4];
            split2(sacc[2 * kc][0], sacc[2 * kc][1], pah[0], pal[0]);
            split2(sacc[2 * kc][2], sacc[2 * kc][3], pah[1], pal[1]);
            split2(sacc[2 * kc + 1][0], sacc[2 * kc + 1][1], pah[2], pal[2]);
            split2(sacc[2 * kc + 1][2], sacc[2 * kc + 1][3], pah[3], pal[3]);

            uint32_t vhf[8][2], vlf[8][2];
#pragma unroll
            for (int ntp = 0; ntp < 4; ntp++) {
                const int key = 16 * kc + (sel & 1) * 8 + localr;
                const int dim = (2 * ntp + (sel >> 1)) * 8;
                const uint32_t off = SWZ((uint32_t)(key * 128 + dim * 2));
                uint32_t t0r, t1r, t2r, t3r;
                LDSM_X4_T(t0r, t1r, t2r, t3r, stb + A_VH + off);
                vhf[2 * ntp][0] = t0r; vhf[2 * ntp][1] = t1r;
                vhf[2 * ntp + 1][0] = t2r; vhf[2 * ntp + 1][1] = t3r;
                LDSM_X4_T(t0r, t1r, t2r, t3r, stb + A_VL + off);
                vlf[2 * ntp][0] = t0r; vlf[2 * ntp][1] = t1r;
                vlf[2 * ntp + 1][0] = t2r; vlf[2 * ntp + 1][1] = t3r;
            }
#pragma unroll
            for (int nt = 0; nt < 8; nt++)
                MMA16816(oacc[nt], pah, vhf[nt]);
#pragma unroll
            for (int nt = 0; nt < 8; nt++)
                MMA16816(oacc[nt], pah, vlf[nt]);
#pragma unroll
            for (int nt = 0; nt < 8; nt++)
                MMA16816(oacc[nt], pal, vhf[nt]);
        }
    }

    // ---- epilogue: normalize, blend weight, write bf16 hi/lo ----
    l0 += __shfl_xor_sync(0xffffffffu, l0, 1);
    l0 += __shfl_xor_sync(0xffffffffu, l0, 2);
    l1 += __shfl_xor_sync(0xffffffffu, l1, 1);
    l1 += __shfl_xor_sync(0xffffffffu, l1, 2);
    float w0 = 1.f, w1 = 1.f;
    if (q0 >= SS - 128) w0 = 1.f + (float)(q0 - (SS - 128)) * (1.f / 127.f);
    if (q1 >= SS - 128) w1 = 1.f + (float)(q1 - (SS - 128)) * (1.f / 127.f);
    const float sc0 = w0 / l0, sc1 = w1 / l1;
    const int ec = 2 * (lane & 3);
#pragma unroll
    for (int nt = 0; nt < 8; nt++) {
        const size_t i0 = (size_t)q0 * DD + hoff + 8 * nt + ec;
        const size_t i1 = (size_t)q1 * DD + hoff + 8 * nt + ec;
        uint32_t h0, l0u, h1, l1u;
        split2(oacc[nt][0] * sc0, oacc[nt][1] * sc0, h0, l0u);
        split2(oacc[nt][2] * sc1, oacc[nt][3] * sc1, h1, l1u);
        *(uint32_t*)&Oh[i0] = h0;
        *(uint32_t*)&Ol[i0] = l0u;
        *(uint32_t*)&Oh[i1] = h1;
        *(uint32_t*)&Ol[i1] = l1u;
    }
}

// ===========================================================================
extern "C" void kernel_launch(void* const* d_in, const int* in_sizes, int n_in,
                              void* d_out, int out_size) {
    const float* x = nullptr;
    const float* Wm[4] = {nullptr, nullptr, nullptr, nullptr};
    const float* bm[4] = {nullptr, nullptr, nullptr, nullptr};
    int nw = 0, nb = 0;
    for (int i = 0; i < n_in; i++) {
        const float* p = (const float*)d_in[i];
        if (in_sizes[i] == SS * DD) x = p;
        else if (in_sizes[i] == DD * DD) { if (nw < 4) Wm[nw++] = p; }
        else if (in_sizes[i] == DD) { if (nb < 4) bm[nb++] = p; }
    }
    float* out = (float*)d_out;

    __nv_bfloat16 *xh, *xl, *Wh, *Wl, *Qh, *Ql, *Kh, *Kl, *Vh, *Vl, *Oh, *Ol;
    cudaGetSymbolAddress((void**)&xh, g_xh);
    cudaGetSymbolAddress((void**)&xl, g_xl);
    cudaGetSymbolAddress((void**)&Wh, g_Wh);
    cudaGetSymbolAddress((void**)&Wl, g_Wl);
    cudaGetSymbolAddress((void**)&Qh, g_Qh);
    cudaGetSymbolAddress((void**)&Ql, g_Ql);
    cudaGetSymbolAddress((void**)&Kh, g_Kh);
    cudaGetSymbolAddress((void**)&Kl, g_Kl);
    cudaGetSymbolAddress((void**)&Vh, g_Vh);
    cudaGetSymbolAddress((void**)&Vl, g_Vl);
    cudaGetSymbolAddress((void**)&Oh, g_Oh);
    cudaGetSymbolAddress((void**)&Ol, g_Ol);

    // ---- fused split of x and all 4 weights (one launch) ----
    const int NTOT = NX8 + 4 * NW8;
    split_all<<<(NTOT + 255) / 256, 256>>>(x, Wm[0], Wm[1], Wm[2], Wm[3],
                                           xh, xl, Wh, Wl);

    cudaFuncSetAttribute(gemm_qkv, cudaFuncAttributeMaxDynamicSharedMemorySize,
                         GEMM_SMEM);
    cudaFuncSetAttribute(gemm_out, cudaFuncAttributeMaxDynamicSharedMemorySize,
                         GEMM_SMEM);
    cudaFuncSetAttribute(attn_mma, cudaFuncAttributeMaxDynamicSharedMemorySize,
                         ATT_SMEM);

    // ---- fused Q/K/V projections ----
    QKVArgs qa;
    qa.Bh[0] = Wh;                       qa.Bl[0] = Wl;
    qa.Bh[1] = Wh + (size_t)1 * DD * DD; qa.Bl[1] = Wl + (size_t)1 * DD * DD;
    qa.Bh[2] = Wh + (size_t)2 * DD * DD; qa.Bl[2] = Wl + (size_t)2 * DD * DD;
    qa.bias[0] = bm[0]; qa.bias[1] = bm[1]; qa.bias[2] = bm[2];
    qa.Ch[0] = Qh; qa.Cl[0] = Ql;
    qa.Ch[1] = Kh; qa.Cl[1] = Kl;
    qa.Ch[2] = Vh; qa.Cl[2] = Vl;

    dim3 qkvgrid(DD / 128, SS / 128, 3);
    gemm_qkv<<<qkvgrid, 256, GEMM_SMEM>>>(xh, xl, qa);

    attn_mma<<<dim3(SS / 128, HH), 256, ATT_SMEM>>>(Qh, Ql, Kh, Kl, Vh, Vl,
                                                    Oh, Ol);

    dim3 ogrid(DD / 128, SS / 128);
    gemm_out<<<ogrid, 256, GEMM_SMEM>>>(Oh, Ol, Wh + (size_t)3 * DD * DD,
                                        Wl + (size_t)3 * DD * DD, bm[3], out);
}

// round 14
// speedup vs baseline: 1.3731x; 1.3495x over previous
#include <cuda_runtime.h>
#include <cuda_fp16.h>
#include <stdint.h>
#include <math.h>

#define SS 8192
#define DD 1024
#define HH 16
#define HDIM 64

// ---- scratch: fp16 operands (static device arrays) ----
__device__ __half g_xh[SS * DD], g_xl[SS * DD];
__device__ __half g_Wh[4][DD * DD];            // weights: hi only
__device__ __half g_Qh[SS * DD], g_Ql[SS * DD];
__device__ __half g_Kh[SS * DD];               // K: hi only
__device__ __half g_Vh[SS * DD];               // V: hi only
__device__ __half g_Oh[SS * DD], g_Ol[SS * DD];

// ===========================================================================
// PTX helpers (baseline ISA: ldmatrix + mma.sync + cp.async, sm_80+)
// ===========================================================================
__device__ __forceinline__ uint32_t smem_u32(const void* p) {
    uint32_t a;
    asm("{ .reg .u64 t; cvta.to.shared.u64 t, %1; cvt.u32.u64 %0, t; }"
        : "=r"(a) : "l"(p));
    return a;
}

#define LDSM_X4(r0, r1, r2, r3, addr)                                       \
    asm volatile(                                                           \
        "ldmatrix.sync.aligned.m8n8.x4.shared.b16 {%0, %1, %2, %3}, [%4];"  \
        : "=r"(r0), "=r"(r1), "=r"(r2), "=r"(r3) : "r"(addr))

#define LDSM_X4_T(r0, r1, r2, r3, addr)                                     \
    asm volatile(                                                           \
        "ldmatrix.sync.aligned.m8n8.x4.trans.shared.b16 {%0, %1, %2, %3}, [%4];" \
        : "=r"(r0), "=r"(r1), "=r"(r2), "=r"(r3) : "r"(addr))

#define MMA16816(d, a, b)                                                   \
    asm volatile(                                                           \
        "mma.sync.aligned.m16n8k16.row.col.f32.f16.f16.f32 "                \
        "{%0, %1, %2, %3}, {%4, %5, %6, %7}, {%8, %9}, {%0, %1, %2, %3};"   \
        : "+f"((d)[0]), "+f"((d)[1]), "+f"((d)[2]), "+f"((d)[3])            \
        : "r"((a)[0]), "r"((a)[1]), "r"((a)[2]), "r"((a)[3]),               \
          "r"((b)[0]), "r"((b)[1]))

#define CPA16(dst, src, sz)                                                 \
    asm volatile("cp.async.cg.shared.global [%0], [%1], 16, %2;"            \
                 :: "r"(dst), "l"(src), "r"(sz))
#define CPA_COMMIT() asm volatile("cp.async.commit_group;" ::: "memory")
#define CPA_WAIT1()  asm volatile("cp.async.wait_group 1;" ::: "memory")
#define CPA_WAIT0()  asm volatile("cp.async.wait_group 0;" ::: "memory")

#define SWZ(o)   ((o) ^ (((o) >> 3) & 0x70))   // 128B rows
#define SWZ64(o) ((o) ^ (((o) >> 3) & 0x30))   // 64B rows

// Single-instruction fp16x2 pack, round-to-nearest.
__device__ __forceinline__ uint32_t packh(float x, float y) {
    __half2 t = __floats2half2_rn(x, y);
    return *(uint32_t*)&t;
}
// hi/lo split of a float pair into fp16: h = rn(x,y); l = rn(residues).
__device__ __forceinline__ void split2h(float x, float y,
                                        uint32_t& h, uint32_t& l) {
    h = packh(x, y);
    __half2 hv = *(__half2*)&h;
    l = packh(x - __low2float(hv), y - __high2float(hv));
}

// ===========================================================================
// Fused fp32 -> fp16 split: x -> hi/lo, W0..3 -> hi only (one launch).
// ===========================================================================
#define NX8 (SS * DD / 8)
#define NW8 (DD * DD / 8)

__global__ void split_all(const float* __restrict__ x,
                          const float* __restrict__ w0,
                          const float* __restrict__ w1,
                          const float* __restrict__ w2,
                          const float* __restrict__ w3,
                          __half* __restrict__ xh,
                          __half* __restrict__ xl,
                          __half* __restrict__ Wh) {
    int idx = blockIdx.x * blockDim.x + threadIdx.x;
    if (idx < NX8) {
        const float4* p = (const float4*)x + (size_t)idx * 2;
        float4 v0 = p[0], v1 = p[1];
        uint32_t h[4], l[4];
        split2h(v0.x, v0.y, h[0], l[0]);
        split2h(v0.z, v0.w, h[1], l[1]);
        split2h(v1.x, v1.y, h[2], l[2]);
        split2h(v1.z, v1.w, h[3], l[3]);
        ((uint4*)xh)[idx] = *(uint4*)h;
        ((uint4*)xl)[idx] = *(uint4*)l;
    } else if (idx < NX8 + 4 * NW8) {
        int r = idx - NX8;
        int w = r >> 17;           // / NW8 (2^17)
        int o = r & (NW8 - 1);
        const float* ws[4] = {w0, w1, w2, w3};
        const float4* p = (const float4*)ws[w] + (size_t)o * 2;
        float4 v0 = p[0], v1 = p[1];
        uint32_t h[4];
        h[0] = packh(v0.x, v0.y);
        h[1] = packh(v0.z, v0.w);
        h[2] = packh(v1.x, v1.y);
        h[3] = packh(v1.z, v1.w);
        ((uint4*)(Wh + (size_t)w * DD * DD))[o] = *(uint4*)h;
    }
}

// ===========================================================================
// Shared GEMM core: mma.sync fp16 2-product ((Ah+Al)*Bh), fp32 accum,
// 3-stage cp.async, occ 2. C[m,n] = sum_k A[m,k]*W[n,k] + bias[n]
// CTA 128x128, K-chunk 32 (64B rows, SW64), 256 threads (8 warps 32m x 64n).
// outmode: 0 = fp32 C, 1 = fp16 hi/lo pair, 2 = fp16 hi only.
// ===========================================================================
#define G_ST(s)  (1024 + (s) * 24576)
#define G_AH 0
#define G_AL 8192
#define G_BH 16384
#define GEMM_SMEM (1024 + 3 * 24576)
#define NCHUNK 32

__device__ __forceinline__ void gemm_core(
    const __half* __restrict__ Ah, const __half* __restrict__ Al,
    const __half* __restrict__ Bh,
    const float* __restrict__ bias, float* __restrict__ C,
    __half* __restrict__ Ch, __half* __restrict__ Cl,
    int outmode, char* sm) {
    const uint32_t sbase = smem_u32(sm);
    float* sbias = (float*)sm;

    const int tid = threadIdx.x;
    const int wid = tid >> 5, lane = tid & 31;
    const int n0 = blockIdx.x * 128, m0 = blockIdx.y * 128;

    if (tid < 128) sbias[tid] = bias[n0 + tid];

    const int wm = (wid & 3) * 32;
    const int wn = (wid >> 2) * 64;

    float acc[2][8][4];
#pragma unroll
    for (int mt = 0; mt < 2; mt++)
#pragma unroll
        for (int nt = 0; nt < 8; nt++)
#pragma unroll
            for (int e = 0; e < 4; e++) acc[mt][nt][e] = 0.f;

    const int cr = tid >> 1;
    const int hcE = (tid & 1) * 16;
    const int localr = lane & 7, sel = lane >> 3;

    const __half* rowA_h = Ah + (size_t)(m0 + cr) * DD + hcE;
    const __half* rowA_l = Al + (size_t)(m0 + cr) * DD + hcE;
    const __half* rowB_h = Bh + (size_t)(n0 + cr) * DD + hcE;

#define G_STAGE(c, s)                                                       \
    do {                                                                    \
        const uint32_t stb = sbase + G_ST(s);                               \
        _Pragma("unroll")                                                   \
        for (int j = 0; j < 2; j++) {                                       \
            uint32_t off = SWZ64((uint32_t)(cr * 64 + hcE * 2 + 16 * j));   \
            CPA16(stb + G_AH + off, rowA_h + (size_t)(c) * 32 + 8 * j, 16); \
            CPA16(stb + G_AL + off, rowA_l + (size_t)(c) * 32 + 8 * j, 16); \
            CPA16(stb + G_BH + off, rowB_h + (size_t)(c) * 32 + 8 * j, 16); \
        }                                                                   \
        CPA_COMMIT();                                                       \
    } while (0)

    G_STAGE(0, 0);
    G_STAGE(1, 1);

    for (int c = 0; c < NCHUNK; c++) {
        const int s = c % 3;
        if (c + 1 < NCHUNK) CPA_WAIT1(); else CPA_WAIT0();
        __syncthreads();
        if (c + 2 < NCHUNK) G_STAGE(c + 2, (c + 2) % 3);

        const uint32_t stb = sbase + G_ST(s);
#pragma unroll
        for (int kk = 0; kk < 32; kk += 16) {
            uint32_t ah[2][4], al[2][4];
#pragma unroll
            for (int mt = 0; mt < 2; mt++) {
                const int row = wm + mt * 16 + localr + (sel & 1) * 8;
                const int kb = kk + (sel >> 1) * 8;
                const uint32_t off = SWZ64((uint32_t)(row * 64 + kb * 2));
                LDSM_X4(ah[mt][0], ah[mt][1], ah[mt][2], ah[mt][3],
                        stb + G_AH + off);
                LDSM_X4(al[mt][0], al[mt][1], al[mt][2], al[mt][3],
                        stb + G_AL + off);
            }
            uint32_t bh[8][2];
#pragma unroll
            for (int np = 0; np < 4; np++) {
                const int row = wn + np * 16 + (sel >> 1) * 8 + localr;
                const int kb = kk + (sel & 1) * 8;
                const uint32_t off = SWZ64((uint32_t)(row * 64 + kb * 2));
                uint32_t t0, t1, t2, t3;
                LDSM_X4(t0, t1, t2, t3, stb + G_BH + off);
                bh[2 * np][0] = t0; bh[2 * np][1] = t1;
                bh[2 * np + 1][0] = t2; bh[2 * np + 1][1] = t3;
            }
            // 2 product passes: (ah + al) * bh
#pragma unroll
            for (int mt = 0; mt < 2; mt++)
#pragma unroll
                for (int nt = 0; nt < 8; nt++)
                    MMA16816(acc[mt][nt], ah[mt], bh[nt]);
#pragma unroll
            for (int mt = 0; mt < 2; mt++)
#pragma unroll
                for (int nt = 0; nt < 8; nt++)
                    MMA16816(acc[mt][nt], al[mt], bh[nt]);
        }
    }

    const int er = lane >> 2;
    const int ec = (lane & 3) * 2;
#pragma unroll
    for (int mt = 0; mt < 2; mt++) {
#pragma unroll
        for (int nt = 0; nt < 8; nt++) {
            const int ct = wn + nt * 8 + ec;
            const int row0 = m0 + wm + mt * 16 + er;
            float x0 = acc[mt][nt][0] + sbias[ct];
            float x1 = acc[mt][nt][1] + sbias[ct + 1];
            float x2 = acc[mt][nt][2] + sbias[ct];
            float x3 = acc[mt][nt][3] + sbias[ct + 1];
            const size_t i0 = (size_t)row0 * DD + n0 + ct;
            const size_t i1 = (size_t)(row0 + 8) * DD + n0 + ct;
            if (outmode == 0) {
                float2 v0 = {x0, x1}, v1 = {x2, x3};
                *(float2*)&C[i0] = v0;
                *(float2*)&C[i1] = v1;
            } else if (outmode == 1) {
                uint32_t h0, l0u, h1, l1u;
                split2h(x0, x1, h0, l0u);
                split2h(x2, x3, h1, l1u);
                *(uint32_t*)&Ch[i0] = h0;
                *(uint32_t*)&Cl[i0] = l0u;
                *(uint32_t*)&Ch[i1] = h1;
                *(uint32_t*)&Cl[i1] = l1u;
            } else {
                *(uint32_t*)&Ch[i0] = packh(x0, x1);
                *(uint32_t*)&Ch[i1] = packh(x2, x3);
            }
        }
    }
#undef G_STAGE
}

// Fused Q/K/V projections: blockIdx.z selects weight/bias/output.
// z==0 (Q): hi/lo out. z==1,2 (K,V): hi only.
struct QKVArgs {
    const __half* Bh[3];
    const float* bias[3];
    __half* Ch[3];
    __half* Cl;   // Q lo only
};

__global__ __launch_bounds__(256, 2)
void gemm_qkv(const __half* __restrict__ Ah,
              const __half* __restrict__ Al, QKVArgs a) {
    extern __shared__ char sm[];
    const int w = blockIdx.z;
    gemm_core(Ah, Al, a.Bh[w], a.bias[w], nullptr,
              a.Ch[w], (w == 0) ? a.Cl : nullptr, (w == 0) ? 1 : 2, sm);
}

__global__ __launch_bounds__(256, 2)
void gemm_out(const __half* __restrict__ Ah,
              const __half* __restrict__ Al,
              const __half* __restrict__ Bh,
              const float* __restrict__ bias, float* __restrict__ C) {
    extern __shared__ char sm[];
    gemm_core(Ah, Al, Bh, bias, C, nullptr, nullptr, 0, sm);
}

// ===========================================================================
// mma.sync sliding-window flash attention, fp16 2-product, 2-stage cp.async,
// online softmax (exp2 domain), interior-tile mask fast path.
// CTA = 128 queries x 1 head, 8 warps (16 q-rows each).
// smem: Q hi/lo 32KB @0; stage s @ 32768 + s*16384 {KH 8KB, VH 8KB}.
// ===========================================================================
#define A_QH 0
#define A_QL 16384
#define A_ST(s) (32768 + (s) * 16384)
#define A_KH 0
#define A_VH 8192
#define ATT_SMEM (32768 + 2 * 16384)
#define SC2 (0.125f * 1.44269504f)   // score scale folded with log2(e)

__global__ __launch_bounds__(256, 2)
void attn_mma(const __half* __restrict__ Qh,
              const __half* __restrict__ Ql,
              const __half* __restrict__ Kh,
              const __half* __restrict__ Vh,
              __half* __restrict__ Oh,
              __half* __restrict__ Ol) {
    extern __shared__ char sm[];
    const uint32_t sbase = smem_u32(sm);

    const int tid = threadIdx.x;
    const int wid = tid >> 5, lane = tid & 31;
    const int qs = blockIdx.x * 128;
    const int hoff = blockIdx.y * HDIM;
    const int localr = lane & 7, sel = lane >> 3;

    // ---- stage Q tile (128 x 64 fp16 hi/lo), swizzled 128B rows ----
    {
        const int r = tid >> 1;
        const int half = (tid & 1) * 32;
        const size_t g = (size_t)(qs + r) * DD + hoff + half;
#pragma unroll
        for (int j = 0; j < 4; j++) {
            uint32_t off = SWZ((uint32_t)(r * 128 + (half + 8 * j) * 2));
            *(uint4*)(sm + A_QH + off) = *(const uint4*)&Qh[g + 8 * j];
            *(uint4*)(sm + A_QL + off) = *(const uint4*)&Ql[g + 8 * j];
        }
    }

    const int t0v = max(0, (512 - qs + 63) / 64);
    const int t1v = min(18, (SS + 512 - qs) / 64);

    const int svr = tid >> 2;
    const int svc = (tid & 3) * 16;

#define A_STAGE(t, s)                                                       \
    do {                                                                    \
        const int kabs_ = qs - 512 + 64 * (t) + svr;                        \
        const size_t g_ = (size_t)kabs_ * DD + hoff + svc;                  \
        const uint32_t stb_ = sbase + A_ST(s);                              \
        _Pragma("unroll")                                                   \
        for (int j = 0; j < 2; j++) {                                       \
            uint32_t off = SWZ((uint32_t)(svr * 128 + (svc + 8 * j) * 2));  \
            CPA16(stb_ + A_KH + off, &Kh[g_ + 8 * j], 16u);                 \
            CPA16(stb_ + A_VH + off, &Vh[g_ + 8 * j], 16u);                 \
        }                                                                   \
        CPA_COMMIT();                                                       \
    } while (0)

    const int q0 = qs + 16 * wid + (lane >> 2);
    const int q1 = q0 + 8;

    float m0 = -1e30f, m1 = -1e30f, l0 = 0.f, l1 = 0.f;
    float oacc[8][4];
#pragma unroll
    for (int nt = 0; nt < 8; nt++)
#pragma unroll
        for (int e = 0; e < 4; e++) oacc[nt][e] = 0.f;

    A_STAGE(t0v, 0);

    for (int t = t0v; t < t1v; t++) {
        const int s = (t - t0v) & 1;
        const int kt = qs - 512 + 64 * t;
        CPA_WAIT0();
        __syncthreads();
        if (t + 1 < t1v) A_STAGE(t + 1, s ^ 1);

        const uint32_t stb = sbase + A_ST(s);

        // ---- QK^T: S (16q x 64k per warp), 2 product passes ----
        float sacc[8][4];
#pragma unroll
        for (int nt = 0; nt < 8; nt++)
#pragma unroll
            for (int e = 0; e < 4; e++) sacc[nt][e] = 0.f;

#pragma unroll
        for (int kk = 0; kk < 64; kk += 16) {
            uint32_t qhf[4], qlf[4];
            {
                const int row = 16 * wid + localr + (sel & 1) * 8;
                const int kb = kk + (sel >> 1) * 8;
                const uint32_t off = SWZ((uint32_t)(row * 128 + kb * 2));
                LDSM_X4(qhf[0], qhf[1], qhf[2], qhf[3], sbase + A_QH + off);
                LDSM_X4(qlf[0], qlf[1], qlf[2], qlf[3], sbase + A_QL + off);
            }
            uint32_t khf[8][2];
#pragma unroll
            for (int np = 0; np < 4; np++) {
                const int row = np * 16 + (sel >> 1) * 8 + localr;
                const int kb = kk + (sel & 1) * 8;
                const uint32_t off = SWZ((uint32_t)(row * 128 + kb * 2));
                uint32_t t0r, t1r, t2r, t3r;
                LDSM_X4(t0r, t1r, t2r, t3r, stb + A_KH + off);
                khf[2 * np][0] = t0r; khf[2 * np][1] = t1r;
                khf[2 * np + 1][0] = t2r; khf[2 * np + 1][1] = t3r;
            }
#pragma unroll
            for (int nt = 0; nt < 8; nt++)
                MMA16816(sacc[nt], qhf, khf[nt]);
#pragma unroll
            for (int nt = 0; nt < 8; nt++)
                MMA16816(sacc[nt], qlf, khf[nt]);
        }

        // ---- scale to exp2 domain (+ window mask on edge tiles) + max ----
        float mx0 = -1e30f, mx1 = -1e30f;
        if (t < 2 || t > 15) {
            const int cb = kt + 2 * (lane & 3);
#pragma unroll
            for (int nt = 0; nt < 8; nt++) {
#pragma unroll
                for (int e = 0; e < 2; e++) {
                    const int kabs = cb + 8 * nt + e;
                    float s0 = ((kabs >= q0 - 512) & (kabs < q0 + 512))
                                   ? sacc[nt][e] * SC2 : -1e30f;
                    float s1 = ((kabs >= q1 - 512) & (kabs < q1 + 512))
                                   ? sacc[nt][e + 2] * SC2 : -1e30f;
                    sacc[nt][e] = s0; sacc[nt][e + 2] = s1;
                    mx0 = fmaxf(mx0, s0); mx1 = fmaxf(mx1, s1);
                }
            }
        } else {
#pragma unroll
            for (int nt = 0; nt < 8; nt++) {
#pragma unroll
                for (int e = 0; e < 2; e++) {
                    float s0 = sacc[nt][e] * SC2;
                    float s1 = sacc[nt][e + 2] * SC2;
                    sacc[nt][e] = s0; sacc[nt][e + 2] = s1;
                    mx0 = fmaxf(mx0, s0); mx1 = fmaxf(mx1, s1);
                }
            }
        }
        mx0 = fmaxf(mx0, __shfl_xor_sync(0xffffffffu, mx0, 1));
        mx0 = fmaxf(mx0, __shfl_xor_sync(0xffffffffu, mx0, 2));
        mx1 = fmaxf(mx1, __shfl_xor_sync(0xffffffffu, mx1, 1));
        mx1 = fmaxf(mx1, __shfl_xor_sync(0xffffffffu, mx1, 2));
        const float mn0 = fmaxf(m0, mx0), mn1 = fmaxf(m1, mx1);
        const float a0 = exp2f(m0 - mn0), a1 = exp2f(m1 - mn1);
        m0 = mn0; m1 = mn1;
        float rs0 = 0.f, rs1 = 0.f;
#pragma unroll
        for (int nt = 0; nt < 8; nt++) {
#pragma unroll
            for (int e = 0; e < 2; e++) {
                float p0 = (sacc[nt][e] > -5e29f) ? exp2f(sacc[nt][e] - mn0) : 0.f;
                float p1 = (sacc[nt][e + 2] > -5e29f) ? exp2f(sacc[nt][e + 2] - mn1) : 0.f;
                rs0 += p0; rs1 += p1;
                sacc[nt][e] = p0; sacc[nt][e + 2] = p1;
            }
        }
        l0 = l0 * a0 + rs0;
        l1 = l1 * a1 + rs1;
#pragma unroll
        for (int nt = 0; nt < 8; nt++) {
            oacc[nt][0] *= a0; oacc[nt][1] *= a0;
            oacc[nt][2] *= a1; oacc[nt][3] *= a1;
        }

        // ---- PV: O += P * V, 2 product passes ----
#pragma unroll
        for (int kc = 0; kc < 4; kc++) {
            uint32_t pah[4], pal[4];
            split2h(sacc[2 * kc][0], sacc[2 * kc][1], pah[0], pal[0]);
            split2h(sacc[2 * kc][2], sacc[2 * kc][3], pah[1], pal[1]);
            split2h(sacc[2 * kc + 1][0], sacc[2 * kc + 1][1], pah[2], pal[2]);
            split2h(sacc[2 * kc + 1][2], sacc[2 * kc + 1][3], pah[3], pal[3]);

            uint32_t vhf[8][2];
#pragma unroll
            for (int ntp = 0; ntp < 4; ntp++) {
                const int key = 16 * kc + (sel & 1) * 8 + localr;
                const int dim = (2 * ntp + (sel >> 1)) * 8;
                const uint32_t off = SWZ((uint32_t)(key * 128 + dim * 2));
                uint32_t t0r, t1r, t2r, t3r;
                LDSM_X4_T(t0r, t1r, t2r, t3r, stb + A_VH + off);
                vhf[2 * ntp][0] = t0r; vhf[2 * ntp][1] = t1r;
                vhf[2 * ntp + 1][0] = t2r; vhf[2 * ntp + 1][1] = t3r;
            }
#pragma unroll
            for (int nt = 0; nt < 8; nt++)
                MMA16816(oacc[nt], pah, vhf[nt]);
#pragma unroll
            for (int nt = 0; nt < 8; nt++)
                MMA16816(oacc[nt], pal, vhf[nt]);
        }
    }

    // ---- epilogue: normalize, blend weight, write fp16 hi/lo ----
    l0 += __shfl_xor_sync(0xffffffffu, l0, 1);
    l0 += __shfl_xor_sync(0xffffffffu, l0, 2);
    l1 += __shfl_xor_sync(0xffffffffu, l1, 1);
    l1 += __shfl_xor_sync(0xffffffffu, l1, 2);
    float w0 = 1.f, w1 = 1.f;
    if (q0 >= SS - 128) w0 = 1.f + (float)(q0 - (SS - 128)) * (1.f / 127.f);
    if (q1 >= SS - 128) w1 = 1.f + (float)(q1 - (SS - 128)) * (1.f / 127.f);
    const float sc0 = w0 / l0, sc1 = w1 / l1;
    const int ec = 2 * (lane & 3);
#pragma unroll
    for (int nt = 0; nt < 8; nt++) {
        const size_t i0 = (size_t)q0 * DD + hoff + 8 * nt + ec;
        const size_t i1 = (size_t)q1 * DD + hoff + 8 * nt + ec;
        uint32_t h0, l0u, h1, l1u;
        split2h(oacc[nt][0] * sc0, oacc[nt][1] * sc0, h0, l0u);
        split2h(oacc[nt][2] * sc1, oacc[nt][3] * sc1, h1, l1u);
        *(uint32_t*)&Oh[i0] = h0;
        *(uint32_t*)&Ol[i0] = l0u;
        *(uint32_t*)&Oh[i1] = h1;
        *(uint32_t*)&Ol[i1] = l1u;
    }
}

// ===========================================================================
extern "C" void kernel_launch(void* const* d_in, const int* in_sizes, int n_in,
                              void* d_out, int out_size) {
    const float* x = nullptr;
    const float* Wm[4] = {nullptr, nullptr, nullptr, nullptr};
    const float* bm[4] = {nullptr, nullptr, nullptr, nullptr};
    int nw = 0, nb = 0;
    for (int i = 0; i < n_in; i++) {
        const float* p = (const float*)d_in[i];
        if (in_sizes[i] == SS * DD) x = p;
        else if (in_sizes[i] == DD * DD) { if (nw < 4) Wm[nw++] = p; }
        else if (in_sizes[i] == DD) { if (nb < 4) bm[nb++] = p; }
    }
    float* out = (float*)d_out;

    __half *xh, *xl, *Wh, *Qh, *Ql, *Kh, *Vh, *Oh, *Ol;
    cudaGetSymbolAddress((void**)&xh, g_xh);
    cudaGetSymbolAddress((void**)&xl, g_xl);
    cudaGetSymbolAddress((void**)&Wh, g_Wh);
    cudaGetSymbolAddress((void**)&Qh, g_Qh);
    cudaGetSymbolAddress((void**)&Ql, g_Ql);
    cudaGetSymbolAddress((void**)&Kh, g_Kh);
    cudaGetSymbolAddress((void**)&Vh, g_Vh);
    cudaGetSymbolAddress((void**)&Oh, g_Oh);
    cudaGetSymbolAddress((void**)&Ol, g_Ol);

    // ---- fused split: x hi/lo + W hi (one launch) ----
    const int NTOT = NX8 + 4 * NW8;
    split_all<<<(NTOT + 255) / 256, 256>>>(x, Wm[0], Wm[1], Wm[2], Wm[3],
                                           xh, xl, Wh);

    cudaFuncSetAttribute(gemm_qkv, cudaFuncAttributeMaxDynamicSharedMemorySize,
                         GEMM_SMEM);
    cudaFuncSetAttribute(gemm_out, cudaFuncAttributeMaxDynamicSharedMemorySize,
                         GEMM_SMEM);
    cudaFuncSetAttribute(attn_mma, cudaFuncAttributeMaxDynamicSharedMemorySize,
                         ATT_SMEM);

    // ---- fused Q/K/V projections ----
    QKVArgs qa;
    qa.Bh[0] = Wh;
    qa.Bh[1] = Wh + (size_t)1 * DD * DD;
    qa.Bh[2] = Wh + (size_t)2 * DD * DD;
    qa.bias[0] = bm[0]; qa.bias[1] = bm[1]; qa.bias[2] = bm[2];
    qa.Ch[0] = Qh; qa.Ch[1] = Kh; qa.Ch[2] = Vh;
    qa.Cl = Ql;

    dim3 qkvgrid(DD / 128, SS / 128, 3);
    gemm_qkv<<<qkvgrid, 256, GEMM_SMEM>>>(xh, xl, qa);

    attn_mma<<<dim3(SS / 128, HH), 256, ATT_SMEM>>>(Qh, Ql, Kh, Vh, Oh, Ol);

    dim3 ogrid(DD / 128, SS / 128);
    gemm_out<<<ogrid, 256, GEMM_SMEM>>>(Oh, Ol, Wh + (size_t)3 * DD * DD,
                                        bm[3], out);
}

// round 15
// speedup vs baseline: 1.4061x; 1.0240x over previous
#include <cuda_runtime.h>
#include <cuda_fp16.h>
#include <stdint.h>
#include <math.h>

#define SS 8192
#define DD 1024
#define HH 16
#define HDIM 64

// ---- scratch: fp16 operands (static device arrays) ----
__device__ __half g_xh[SS * DD], g_xl[SS * DD];
__device__ __half g_Wh[4][DD * DD];            // weights: hi only
__device__ __half g_Qh[SS * DD], g_Ql[SS * DD];
__device__ __half g_Kh[SS * DD];               // K: hi only
__device__ __half g_Vh[SS * DD];               // V: hi only
__device__ __half g_Oh[SS * DD], g_Ol[SS * DD];

// ===========================================================================
// PTX helpers (baseline ISA: ldmatrix + mma.sync + cp.async, sm_80+)
// ===========================================================================
__device__ __forceinline__ uint32_t smem_u32(const void* p) {
    uint32_t a;
    asm("{ .reg .u64 t; cvta.to.shared.u64 t, %1; cvt.u32.u64 %0, t; }"
        : "=r"(a) : "l"(p));
    return a;
}

#define LDSM_X4(r0, r1, r2, r3, addr)                                       \
    asm volatile(                                                           \
        "ldmatrix.sync.aligned.m8n8.x4.shared.b16 {%0, %1, %2, %3}, [%4];"  \
        : "=r"(r0), "=r"(r1), "=r"(r2), "=r"(r3) : "r"(addr))

#define LDSM_X4_T(r0, r1, r2, r3, addr)                                     \
    asm volatile(                                                           \
        "ldmatrix.sync.aligned.m8n8.x4.trans.shared.b16 {%0, %1, %2, %3}, [%4];" \
        : "=r"(r0), "=r"(r1), "=r"(r2), "=r"(r3) : "r"(addr))

#define MMA16816(d, a, b)                                                   \
    asm volatile(                                                           \
        "mma.sync.aligned.m16n8k16.row.col.f32.f16.f16.f32 "                \
        "{%0, %1, %2, %3}, {%4, %5, %6, %7}, {%8, %9}, {%0, %1, %2, %3};"   \
        : "+f"((d)[0]), "+f"((d)[1]), "+f"((d)[2]), "+f"((d)[3])            \
        : "r"((a)[0]), "r"((a)[1]), "r"((a)[2]), "r"((a)[3]),               \
          "r"((b)[0]), "r"((b)[1]))

#define CPA16(dst, src, sz)                                                 \
    asm volatile("cp.async.cg.shared.global [%0], [%1], 16, %2;"            \
                 :: "r"(dst), "l"(src), "r"(sz))
#define CPA_COMMIT() asm volatile("cp.async.commit_group;" ::: "memory")
#define CPA_WAIT0()  asm volatile("cp.async.wait_group 0;" ::: "memory")

#define SWZ(o)   ((o) ^ (((o) >> 3) & 0x70))   // 128B rows

// Single-instruction fp16x2 pack, round-to-nearest.
__device__ __forceinline__ uint32_t packh(float x, float y) {
    __half2 t = __floats2half2_rn(x, y);
    return *(uint32_t*)&t;
}
// hi/lo split of a float pair into fp16: h = rn(x,y); l = rn(residues).
__device__ __forceinline__ void split2h(float x, float y,
                                        uint32_t& h, uint32_t& l) {
    h = packh(x, y);
    __half2 hv = *(__half2*)&h;
    l = packh(x - __low2float(hv), y - __high2float(hv));
}

#define SC2 (0.125f * 1.44269504f)   // score scale folded with log2(e)

// ===========================================================================
// Fused fp32 -> fp16 split: x -> hi/lo, W0..3 -> hi only (one launch).
// ===========================================================================
#define NX8 (SS * DD / 8)
#define NW8 (DD * DD / 8)

__global__ void split_all(const float* __restrict__ x,
                          const float* __restrict__ w0,
                          const float* __restrict__ w1,
                          const float* __restrict__ w2,
                          const float* __restrict__ w3,
                          __half* __restrict__ xh,
                          __half* __restrict__ xl,
                          __half* __restrict__ Wh) {
    int idx = blockIdx.x * blockDim.x + threadIdx.x;
    if (idx < NX8) {
        const float4* p = (const float4*)x + (size_t)idx * 2;
        float4 v0 = p[0], v1 = p[1];
        uint32_t h[4], l[4];
        split2h(v0.x, v0.y, h[0], l[0]);
        split2h(v0.z, v0.w, h[1], l[1]);
        split2h(v1.x, v1.y, h[2], l[2]);
        split2h(v1.z, v1.w, h[3], l[3]);
        ((uint4*)xh)[idx] = *(uint4*)h;
        ((uint4*)xl)[idx] = *(uint4*)l;
    } else if (idx < NX8 + 4 * NW8) {
        int r = idx - NX8;
        int w = r >> 17;           // / NW8 (2^17)
        int o = r & (NW8 - 1);
        const float* ws[4] = {w0, w1, w2, w3};
        const float4* p = (const float4*)ws[w] + (size_t)o * 2;
        float4 v0 = p[0], v1 = p[1];
        uint32_t h[4];
        h[0] = packh(v0.x, v0.y);
        h[1] = packh(v0.z, v0.w);
        h[2] = packh(v1.x, v1.y);
        h[3] = packh(v1.z, v1.w);
        ((uint4*)(Wh + (size_t)w * DD * DD))[o] = *(uint4*)h;
    }
}

// ===========================================================================
// Shared GEMM core: mma.sync fp16 2-product ((Ah+Al)*Bh), fp32 accum,
// K-chunk 64 (128B rows, SW128), 2-stage cp.async, occ 2.
//   C[m,n] = sum_k A[m,k]*W[n,k] + bias[n]
// CTA 128x128, 256 threads (8 warps 32m x 64n).
// outmode: 0 = fp32 C, 1 = fp16 hi/lo pair (scaled), 2 = fp16 hi only.
// ===========================================================================
#define G_ST(s)  (1024 + (s) * 49152)
#define G_AH 0
#define G_AL 16384
#define G_BH 32768
#define GEMM_SMEM (1024 + 2 * 49152)
#define NCHUNK 16

__device__ __forceinline__ void gemm_core(
    const __half* __restrict__ Ah, const __half* __restrict__ Al,
    const __half* __restrict__ Bh,
    const float* __restrict__ bias, float* __restrict__ C,
    __half* __restrict__ Ch, __half* __restrict__ Cl,
    int outmode, float outscale, char* sm) {
    const uint32_t sbase = smem_u32(sm);
    float* sbias = (float*)sm;

    const int tid = threadIdx.x;
    const int wid = tid >> 5, lane = tid & 31;
    const int n0 = blockIdx.x * 128, m0 = blockIdx.y * 128;

    if (tid < 128) sbias[tid] = bias[n0 + tid];

    const int wm = (wid & 3) * 32;
    const int wn = (wid >> 2) * 64;

    float acc[2][8][4];
#pragma unroll
    for (int mt = 0; mt < 2; mt++)
#pragma unroll
        for (int nt = 0; nt < 8; nt++)
#pragma unroll
            for (int e = 0; e < 4; e++) acc[mt][nt][e] = 0.f;

    const int cr = tid >> 1;                  // row 0..127
    const int hcE = (tid & 1) * 32;           // element offset within 64-elem chunk
    const int localr = lane & 7, sel = lane >> 3;

    const __half* rowA_h = Ah + (size_t)(m0 + cr) * DD + hcE;
    const __half* rowA_l = Al + (size_t)(m0 + cr) * DD + hcE;
    const __half* rowB_h = Bh + (size_t)(n0 + cr) * DD + hcE;

#define G_STAGE(c, s)                                                       \
    do {                                                                    \
        const uint32_t stb = sbase + G_ST(s);                               \
        _Pragma("unroll")                                                   \
        for (int j = 0; j < 4; j++) {                                       \
            uint32_t off = SWZ((uint32_t)(cr * 128 + hcE * 2 + 16 * j));    \
            CPA16(stb + G_AH + off, rowA_h + (size_t)(c) * 64 + 8 * j, 16); \
            CPA16(stb + G_AL + off, rowA_l + (size_t)(c) * 64 + 8 * j, 16); \
            CPA16(stb + G_BH + off, rowB_h + (size_t)(c) * 64 + 8 * j, 16); \
        }                                                                   \
        CPA_COMMIT();                                                       \
    } while (0)

    G_STAGE(0, 0);

    for (int c = 0; c < NCHUNK; c++) {
        const int s = c & 1;
        CPA_WAIT0();
        __syncthreads();
        if (c + 1 < NCHUNK) G_STAGE(c + 1, s ^ 1);

        const uint32_t stb = sbase + G_ST(s);
#pragma unroll
        for (int kk = 0; kk < 64; kk += 16) {
            uint32_t ah[2][4], al[2][4];
#pragma unroll
            for (int mt = 0; mt < 2; mt++) {
                const int row = wm + mt * 16 + localr + (sel & 1) * 8;
                const int kb = kk + (sel >> 1) * 8;
                const uint32_t off = SWZ((uint32_t)(row * 128 + kb * 2));
                LDSM_X4(ah[mt][0], ah[mt][1], ah[mt][2], ah[mt][3],
                        stb + G_AH + off);
                LDSM_X4(al[mt][0], al[mt][1], al[mt][2], al[mt][3],
                        stb + G_AL + off);
            }
            uint32_t bh[8][2];
#pragma unroll
            for (int np = 0; np < 4; np++) {
                const int row = wn + np * 16 + (sel >> 1) * 8 + localr;
                const int kb = kk + (sel & 1) * 8;
                const uint32_t off = SWZ((uint32_t)(row * 128 + kb * 2));
                uint32_t t0, t1, t2, t3;
                LDSM_X4(t0, t1, t2, t3, stb + G_BH + off);
                bh[2 * np][0] = t0; bh[2 * np][1] = t1;
                bh[2 * np + 1][0] = t2; bh[2 * np + 1][1] = t3;
            }
#pragma unroll
            for (int mt = 0; mt < 2; mt++)
#pragma unroll
                for (int nt = 0; nt < 8; nt++)
                    MMA16816(acc[mt][nt], ah[mt], bh[nt]);
#pragma unroll
            for (int mt = 0; mt < 2; mt++)
#pragma unroll
                for (int nt = 0; nt < 8; nt++)
                    MMA16816(acc[mt][nt], al[mt], bh[nt]);
        }
    }

    const int er = lane >> 2;
    const int ec = (lane & 3) * 2;
#pragma unroll
    for (int mt = 0; mt < 2; mt++) {
#pragma unroll
        for (int nt = 0; nt < 8; nt++) {
            const int ct = wn + nt * 8 + ec;
            const int row0 = m0 + wm + mt * 16 + er;
            float x0 = (acc[mt][nt][0] + sbias[ct]) * outscale;
            float x1 = (acc[mt][nt][1] + sbias[ct + 1]) * outscale;
            float x2 = (acc[mt][nt][2] + sbias[ct]) * outscale;
            float x3 = (acc[mt][nt][3] + sbias[ct + 1]) * outscale;
            const size_t i0 = (size_t)row0 * DD + n0 + ct;
            const size_t i1 = (size_t)(row0 + 8) * DD + n0 + ct;
            if (outmode == 0) {
                float2 v0 = {x0, x1}, v1 = {x2, x3};
                *(float2*)&C[i0] = v0;
                *(float2*)&C[i1] = v1;
            } else if (outmode == 1) {
                uint32_t h0, l0u, h1, l1u;
                split2h(x0, x1, h0, l0u);
                split2h(x2, x3, h1, l1u);
                *(uint32_t*)&Ch[i0] = h0;
                *(uint32_t*)&Cl[i0] = l0u;
                *(uint32_t*)&Ch[i1] = h1;
                *(uint32_t*)&Cl[i1] = l1u;
            } else {
                *(uint32_t*)&Ch[i0] = packh(x0, x1);
                *(uint32_t*)&Ch[i1] = packh(x2, x3);
            }
        }
    }
#undef G_STAGE
}

// Fused Q/K/V projections: blockIdx.z selects weight/bias/output.
// z==0 (Q): hi/lo out, pre-scaled by SC2. z==1,2 (K,V): hi only.
struct QKVArgs {
    const __half* Bh[3];
    const float* bias[3];
    __half* Ch[3];
    __half* Cl;   // Q lo only
};

__global__ __launch_bounds__(256, 2)
void gemm_qkv(const __half* __restrict__ Ah,
              const __half* __restrict__ Al, QKVArgs a) {
    extern __shared__ char sm[];
    const int w = blockIdx.z;
    gemm_core(Ah, Al, a.Bh[w], a.bias[w], nullptr,
              a.Ch[w], (w == 0) ? a.Cl : nullptr,
              (w == 0) ? 1 : 2, (w == 0) ? SC2 : 1.0f, sm);
}

__global__ __launch_bounds__(256, 2)
void gemm_out(const __half* __restrict__ Ah,
              const __half* __restrict__ Al,
              const __half* __restrict__ Bh,
              const float* __restrict__ bias, float* __restrict__ C) {
    extern __shared__ char sm[];
    gemm_core(Ah, Al, Bh, bias, C, nullptr, nullptr, 0, 1.0f, sm);
}

// ===========================================================================
// mma.sync sliding-window flash attention, fp16 2-product, 2-stage cp.async,
// online softmax (exp2 domain; Q pre-scaled so scores are already in it),
// interior-tile mask fast path, underflow-based masking (no sentinel tests).
// CTA = 128 queries x 1 head, 8 warps (16 q-rows each).
// ===========================================================================
#define A_QH 0
#define A_QL 16384
#define A_ST(s) (32768 + (s) * 16384)
#define A_KH 0
#define A_VH 8192
#define ATT_SMEM (32768 + 2 * 16384)

__global__ __launch_bounds__(256, 2)
void attn_mma(const __half* __restrict__ Qh,
              const __half* __restrict__ Ql,
              const __half* __restrict__ Kh,
              const __half* __restrict__ Vh,
              __half* __restrict__ Oh,
              __half* __restrict__ Ol) {
    extern __shared__ char sm[];
    const uint32_t sbase = smem_u32(sm);

    const int tid = threadIdx.x;
    const int wid = tid >> 5, lane = tid & 31;
    const int qs = blockIdx.x * 128;
    const int hoff = blockIdx.y * HDIM;
    const int localr = lane & 7, sel = lane >> 3;

    // ---- stage Q tile (128 x 64 fp16 hi/lo), swizzled 128B rows ----
    {
        const int r = tid >> 1;
        const int half = (tid & 1) * 32;
        const size_t g = (size_t)(qs + r) * DD + hoff + half;
#pragma unroll
        for (int j = 0; j < 4; j++) {
            uint32_t off = SWZ((uint32_t)(r * 128 + (half + 8 * j) * 2));
            *(uint4*)(sm + A_QH + off) = *(const uint4*)&Qh[g + 8 * j];
            *(uint4*)(sm + A_QL + off) = *(const uint4*)&Ql[g + 8 * j];
        }
    }

    const int t0v = max(0, (512 - qs + 63) / 64);
    const int t1v = min(18, (SS + 512 - qs) / 64);

    const int svr = tid >> 2;
    const int svc = (tid & 3) * 16;

#define A_STAGE(t, s)                                                       \
    do {                                                                    \
        const int kabs_ = qs - 512 + 64 * (t) + svr;                        \
        const size_t g_ = (size_t)kabs_ * DD + hoff + svc;                  \
        const uint32_t stb_ = sbase + A_ST(s);                              \
        _Pragma("unroll")                                                   \
        for (int j = 0; j < 2; j++) {                                       \
            uint32_t off = SWZ((uint32_t)(svr * 128 + (svc + 8 * j) * 2));  \
            CPA16(stb_ + A_KH + off, &Kh[g_ + 8 * j], 16u);                 \
            CPA16(stb_ + A_VH + off, &Vh[g_ + 8 * j], 16u);                 \
        }                                                                   \
        CPA_COMMIT();                                                       \
    } while (0)

    const int q0 = qs + 16 * wid + (lane >> 2);
    const int q1 = q0 + 8;

    float m0 = -1e30f, m1 = -1e30f, l0 = 0.f, l1 = 0.f;
    float oacc[8][4];
#pragma unroll
    for (int nt = 0; nt < 8; nt++)
#pragma unroll
        for (int e = 0; e < 4; e++) oacc[nt][e] = 0.f;

    A_STAGE(t0v, 0);

    for (int t = t0v; t < t1v; t++) {
        const int s = (t - t0v) & 1;
        const int kt = qs - 512 + 64 * t;
        CPA_WAIT0();
        __syncthreads();
        if (t + 1 < t1v) A_STAGE(t + 1, s ^ 1);

        const uint32_t stb = sbase + A_ST(s);

        // ---- QK^T: S (16q x 64k per warp), 2 product passes ----
        // Q is pre-scaled by 0.125*log2(e): sacc is directly in exp2 domain.
        float sacc[8][4];
#pragma unroll
        for (int nt = 0; nt < 8; nt++)
#pragma unroll
            for (int e = 0; e < 4; e++) sacc[nt][e] = 0.f;

#pragma unroll
        for (int kk = 0; kk < 64; kk += 16) {
            uint32_t qhf[4], qlf[4];
            {
                const int row = 16 * wid + localr + (sel & 1) * 8;
                const int kb = kk + (sel >> 1) * 8;
                const uint32_t off = SWZ((uint32_t)(row * 128 + kb * 2));
                LDSM_X4(qhf[0], qhf[1], qhf[2], qhf[3], sbase + A_QH + off);
                LDSM_X4(qlf[0], qlf[1], qlf[2], qlf[3], sbase + A_QL + off);
            }
            uint32_t khf[8][2];
#pragma unroll
            for (int np = 0; np < 4; np++) {
                const int row = np * 16 + (sel >> 1) * 8 + localr;
                const int kb = kk + (sel & 1) * 8;
                const uint32_t off = SWZ((uint32_t)(row * 128 + kb * 2));
                uint32_t t0r, t1r, t2r, t3r;
                LDSM_X4(t0r, t1r, t2r, t3r, stb + A_KH + off);
                khf[2 * np][0] = t0r; khf[2 * np][1] = t1r;
                khf[2 * np + 1][0] = t2r; khf[2 * np + 1][1] = t3r;
            }
#pragma unroll
            for (int nt = 0; nt < 8; nt++)
                MMA16816(sacc[nt], qhf, khf[nt]);
#pragma unroll
            for (int nt = 0; nt < 8; nt++)
                MMA16816(sacc[nt], qlf, khf[nt]);
        }

        // ---- window mask (edge tiles only) + row max ----
        float mx0 = -1e30f, mx1 = -1e30f;
        if (t < 2 || t > 15) {
            const int cb = kt + 2 * (lane & 3);
#pragma unroll
            for (int nt = 0; nt < 8; nt++) {
#pragma unroll
                for (int e = 0; e < 2; e++) {
                    const int kabs = cb + 8 * nt + e;
                    float s0 = ((kabs >= q0 - 512) & (kabs < q0 + 512))
                                   ? sacc[nt][e] : -1e30f;
                    float s1 = ((kabs >= q1 - 512) & (kabs < q1 + 512))
                                   ? sacc[nt][e + 2] : -1e30f;
                    sacc[nt][e] = s0; sacc[nt][e + 2] = s1;
                    mx0 = fmaxf(mx0, s0); mx1 = fmaxf(mx1, s1);
                }
            }
        } else {
#pragma unroll
            for (int nt = 0; nt < 8; nt++) {
#pragma unroll
                for (int e = 0; e < 2; e++) {
                    mx0 = fmaxf(mx0, sacc[nt][e]);
                    mx1 = fmaxf(mx1, sacc[nt][e + 2]);
                }
            }
        }
        mx0 = fmaxf(mx0, __shfl_xor_sync(0xffffffffu, mx0, 1));
        mx0 = fmaxf(mx0, __shfl_xor_sync(0xffffffffu, mx0, 2));
        mx1 = fmaxf(mx1, __shfl_xor_sync(0xffffffffu, mx1, 1));
        mx1 = fmaxf(mx1, __shfl_xor_sync(0xffffffffu, mx1, 2));
        const float mn0 = fmaxf(m0, mx0), mn1 = fmaxf(m1, mx1);
        const float a0 = exp2f(m0 - mn0), a1 = exp2f(m1 - mn1);
        m0 = mn0; m1 = mn1;
        float rs0 = 0.f, rs1 = 0.f;
        // exp2f(-1e30 - mn) underflows to exactly 0 -> masked lanes drop out.
#pragma unroll
        for (int nt = 0; nt < 8; nt++) {
#pragma unroll
            for (int e = 0; e < 2; e++) {
                float p0 = exp2f(sacc[nt][e] - mn0);
                float p1 = exp2f(sacc[nt][e + 2] - mn1);
                rs0 += p0; rs1 += p1;
                sacc[nt][e] = p0; sacc[nt][e + 2] = p1;
            }
        }
        l0 = l0 * a0 + rs0;
        l1 = l1 * a1 + rs1;
#pragma unroll
        for (int nt = 0; nt < 8; nt++) {
            oacc[nt][0] *= a0; oacc[nt][1] *= a0;
            oacc[nt][2] *= a1; oacc[nt][3] *= a1;
        }

        // ---- PV: O += P * V, 2 product passes ----
#pragma unroll
        for (int kc = 0; kc < 4; kc++) {
            uint32_t pah[4], pal[4];
            split2h(sacc[2 * kc][0], sacc[2 * kc][1], pah[0], pal[0]);
            split2h(sacc[2 * kc][2], sacc[2 * kc][3], pah[1], pal[1]);
            split2h(sacc[2 * kc + 1][0], sacc[2 * kc + 1][1], pah[2], pal[2]);
            split2h(sacc[2 * kc + 1][2], sacc[2 * kc + 1][3], pah[3], pal[3]);

            uint32_t vhf[8][2];
#pragma unroll
            for (int ntp = 0; ntp < 4; ntp++) {
                const int key = 16 * kc + (sel & 1) * 8 + localr;
                const int dim = (2 * ntp + (sel >> 1)) * 8;
                const uint32_t off = SWZ((uint32_t)(key * 128 + dim * 2));
                uint32_t t0r, t1r, t2r, t3r;
                LDSM_X4_T(t0r, t1r, t2r, t3r, stb + A_VH + off);
                vhf[2 * ntp][0] = t0r; vhf[2 * ntp][1] = t1r;
                vhf[2 * ntp + 1][0] = t2r; vhf[2 * ntp + 1][1] = t3r;
            }
#pragma unroll
            for (int nt = 0; nt < 8; nt++)
                MMA16816(oacc[nt], pah, vhf[nt]);
#pragma unroll
            for (int nt = 0; nt < 8; nt++)
                MMA16816(oacc[nt], pal, vhf[nt]);
        }
    }

    // ---- epilogue: normalize, blend weight, write fp16 hi/lo ----
    l0 += __shfl_xor_sync(0xffffffffu, l0, 1);
    l0 += __shfl_xor_sync(0xffffffffu, l0, 2);
    l1 += __shfl_xor_sync(0xffffffffu, l1, 1);
    l1 += __shfl_xor_sync(0xffffffffu, l1, 2);
    float w0 = 1.f, w1 = 1.f;
    if (q0 >= SS - 128) w0 = 1.f + (float)(q0 - (SS - 128)) * (1.f / 127.f);
    if (q1 >= SS - 128) w1 = 1.f + (float)(q1 - (SS - 128)) * (1.f / 127.f);
    const float sc0 = w0 / l0, sc1 = w1 / l1;
    const int ec = 2 * (lane & 3);
#pragma unroll
    for (int nt = 0; nt < 8; nt++) {
        const size_t i0 = (size_t)q0 * DD + hoff + 8 * nt + ec;
        const size_t i1 = (size_t)q1 * DD + hoff + 8 * nt + ec;
        uint32_t h0, l0u, h1, l1u;
        split2h(oacc[nt][0] * sc0, oacc[nt][1] * sc0, h0, l0u);
        split2h(oacc[nt][2] * sc1, oacc[nt][3] * sc1, h1, l1u);
        *(uint32_t*)&Oh[i0] = h0;
        *(uint32_t*)&Ol[i0] = l0u;
        *(uint32_t*)&Oh[i1] = h1;
        *(uint32_t*)&Ol[i1] = l1u;
    }
}

// ===========================================================================
extern "C" void kernel_launch(void* const* d_in, const int* in_sizes, int n_in,
                              void* d_out, int out_size) {
    const float* x = nullptr;
    const float* Wm[4] = {nullptr, nullptr, nullptr, nullptr};
    const float* bm[4] = {nullptr, nullptr, nullptr, nullptr};
    int nw = 0, nb = 0;
    for (int i = 0; i < n_in; i++) {
        const float* p = (const float*)d_in[i];
        if (in_sizes[i] == SS * DD) x = p;
        else if (in_sizes[i] == DD * DD) { if (nw < 4) Wm[nw++] = p; }
        else if (in_sizes[i] == DD) { if (nb < 4) bm[nb++] = p; }
    }
    float* out = (float*)d_out;

    __half *xh, *xl, *Wh, *Qh, *Ql, *Kh, *Vh, *Oh, *Ol;
    cudaGetSymbolAddress((void**)&xh, g_xh);
    cudaGetSymbolAddress((void**)&xl, g_xl);
    cudaGetSymbolAddress((void**)&Wh, g_Wh);
    cudaGetSymbolAddress((void**)&Qh, g_Qh);
    cudaGetSymbolAddress((void**)&Ql, g_Ql);
    cudaGetSymbolAddress((void**)&Kh, g_Kh);
    cudaGetSymbolAddress((void**)&Vh, g_Vh);
    cudaGetSymbolAddress((void**)&Oh, g_Oh);
    cudaGetSymbolAddress((void**)&Ol, g_Ol);

    // ---- fused split: x hi/lo + W hi (one launch) ----
    const int NTOT = NX8 + 4 * NW8;
    split_all<<<(NTOT + 255) / 256, 256>>>(x, Wm[0], Wm[1], Wm[2], Wm[3],
                                           xh, xl, Wh);

    cudaFuncSetAttribute(gemm_qkv, cudaFuncAttributeMaxDynamicSharedMemorySize,
                         GEMM_SMEM);
    cudaFuncSetAttribute(gemm_out, cudaFuncAttributeMaxDynamicSharedMemorySize,
                         GEMM_SMEM);
    cudaFuncSetAttribute(attn_mma, cudaFuncAttributeMaxDynamicSharedMemorySize,
                         ATT_SMEM);

    // ---- fused Q/K/V projections ----
    QKVArgs qa;
    qa.Bh[0] = Wh;
    qa.Bh[1] = Wh + (size_t)1 * DD * DD;
    qa.Bh[2] = Wh + (size_t)2 * DD * DD;
    qa.bias[0] = bm[0]; qa.bias[1] = bm[1]; qa.bias[2] = bm[2];
    qa.Ch[0] = Qh; qa.Ch[1] = Kh; qa.Ch[2] = Vh;
    qa.Cl = Ql;

    dim3 qkvgrid(DD / 128, SS / 128, 3);
    gemm_qkv<<<qkvgrid, 256, GEMM_SMEM>>>(xh, xl, qa);

    attn_mma<<<dim3(SS / 128, HH), 256, ATT_SMEM>>>(Qh, Ql, Kh, Vh, Oh, Ol);

    dim3 ogrid(DD / 128, SS / 128);
    gemm_out<<<ogrid, 256, GEMM_SMEM>>>(Oh, Ol, Wh + (size_t)3 * DD * DD,
                                        bm[3], out);
}

// round 16
// speedup vs baseline: 1.4911x; 1.0604x over previous
#include <cuda_runtime.h>
#include <cuda_fp16.h>
#include <stdint.h>
#include <math.h>

#define SS 8192
#define DD 1024
#define HH 16
#define HDIM 64

// ---- scratch: fp16 operands (static device arrays) ----
__device__ __half g_xh[SS * DD], g_xl[SS * DD];
__device__ __half g_Wh[4][DD * DD];            // weights: hi only
__device__ __half g_Qh[SS * DD], g_Ql[SS * DD];
__device__ __half g_Kh[SS * DD];               // K: hi only
__device__ __half g_Vh[SS * DD];               // V: hi only
__device__ __half g_Oh[SS * DD], g_Ol[SS * DD];

// ===========================================================================
// PTX helpers (baseline ISA: ldmatrix + mma.sync + cp.async, sm_80+)
// ===========================================================================
__device__ __forceinline__ uint32_t smem_u32(const void* p) {
    uint32_t a;
    asm("{ .reg .u64 t; cvta.to.shared.u64 t, %1; cvt.u32.u64 %0, t; }"
        : "=r"(a) : "l"(p));
    return a;
}

#define LDSM_X4(r0, r1, r2, r3, addr)                                       \
    asm volatile(                                                           \
        "ldmatrix.sync.aligned.m8n8.x4.shared.b16 {%0, %1, %2, %3}, [%4];"  \
        : "=r"(r0), "=r"(r1), "=r"(r2), "=r"(r3) : "r"(addr))

#define LDSM_X4_T(r0, r1, r2, r3, addr)                                     \
    asm volatile(                                                           \
        "ldmatrix.sync.aligned.m8n8.x4.trans.shared.b16 {%0, %1, %2, %3}, [%4];" \
        : "=r"(r0), "=r"(r1), "=r"(r2), "=r"(r3) : "r"(addr))

#define MMA16816(d, a, b)                                                   \
    asm volatile(                                                           \
        "mma.sync.aligned.m16n8k16.row.col.f32.f16.f16.f32 "                \
        "{%0, %1, %2, %3}, {%4, %5, %6, %7}, {%8, %9}, {%0, %1, %2, %3};"   \
        : "+f"((d)[0]), "+f"((d)[1]), "+f"((d)[2]), "+f"((d)[3])            \
        : "r"((a)[0]), "r"((a)[1]), "r"((a)[2]), "r"((a)[3]),               \
          "r"((b)[0]), "r"((b)[1]))

#define CPA16(dst, src, sz)                                                 \
    asm volatile("cp.async.cg.shared.global [%0], [%1], 16, %2;"            \
                 :: "r"(dst), "l"(src), "r"(sz))
#define CPA_COMMIT() asm volatile("cp.async.commit_group;" ::: "memory")
#define CPA_WAIT2()  asm volatile("cp.async.wait_group 2;" ::: "memory")
#define CPA_WAIT1()  asm volatile("cp.async.wait_group 1;" ::: "memory")
#define CPA_WAIT0()  asm volatile("cp.async.wait_group 0;" ::: "memory")

#define SWZ(o)   ((o) ^ (((o) >> 3) & 0x70))   // 128B rows
#define SWZ64(o) ((o) ^ (((o) >> 3) & 0x30))   // 64B rows

// Single-instruction fp16x2 pack, round-to-nearest.
__device__ __forceinline__ uint32_t packh(float x, float y) {
    __half2 t = __floats2half2_rn(x, y);
    return *(uint32_t*)&t;
}
// hi/lo split of a float pair into fp16: h = rn(x,y); l = rn(residues).
__device__ __forceinline__ void split2h(float x, float y,
                                        uint32_t& h, uint32_t& l) {
    h = packh(x, y);
    __half2 hv = *(__half2*)&h;
    l = packh(x - __low2float(hv), y - __high2float(hv));
}

#define SC2 (0.125f * 1.44269504f)   // score scale folded with log2(e)

// ===========================================================================
// Fused fp32 -> fp16 split: x -> hi/lo, W0..3 -> hi only (one launch).
// ===========================================================================
#define NX8 (SS * DD / 8)
#define NW8 (DD * DD / 8)

__global__ void split_all(const float* __restrict__ x,
                          const float* __restrict__ w0,
                          const float* __restrict__ w1,
                          const float* __restrict__ w2,
                          const float* __restrict__ w3,
                          __half* __restrict__ xh,
                          __half* __restrict__ xl,
                          __half* __restrict__ Wh) {
    int idx = blockIdx.x * blockDim.x + threadIdx.x;
    if (idx < NX8) {
        const float4* p = (const float4*)x + (size_t)idx * 2;
        float4 v0 = p[0], v1 = p[1];
        uint32_t h[4], l[4];
        split2h(v0.x, v0.y, h[0], l[0]);
        split2h(v0.z, v0.w, h[1], l[1]);
        split2h(v1.x, v1.y, h[2], l[2]);
        split2h(v1.z, v1.w, h[3], l[3]);
        ((uint4*)xh)[idx] = *(uint4*)h;
        ((uint4*)xl)[idx] = *(uint4*)l;
    } else if (idx < NX8 + 4 * NW8) {
        int r = idx - NX8;
        int w = r >> 17;           // / NW8 (2^17)
        int o = r & (NW8 - 1);
        const float* ws[4] = {w0, w1, w2, w3};
        const float4* p = (const float4*)ws[w] + (size_t)o * 2;
        float4 v0 = p[0], v1 = p[1];
        uint32_t h[4];
        h[0] = packh(v0.x, v0.y);
        h[1] = packh(v0.z, v0.w);
        h[2] = packh(v1.x, v1.y);
        h[3] = packh(v1.z, v1.w);
        ((uint4*)(Wh + (size_t)w * DD * DD))[o] = *(uint4*)h;
    }
}

// ===========================================================================
// Shared GEMM core: mma.sync fp16 2-product ((Ah+Al)*Bh), fp32 accum,
// K-chunk 32 (64B rows, SW64), 4-stage cp.async (distance 3), occ 2.
//   C[m,n] = sum_k A[m,k]*W[n,k] + bias[n]
// CTA 128x128, 256 threads (8 warps 32m x 64n).
// outmode: 0 = fp32 C, 1 = fp16 hi/lo pair (scaled), 2 = fp16 hi only.
// ===========================================================================
#define G_ST(s)  (1024 + (s) * 24576)
#define G_AH 0
#define G_AL 8192
#define G_BH 16384
#define GEMM_SMEM (1024 + 4 * 24576)
#define NCHUNK 32

__device__ __forceinline__ void gemm_core(
    const __half* __restrict__ Ah, const __half* __restrict__ Al,
    const __half* __restrict__ Bh,
    const float* __restrict__ bias, float* __restrict__ C,
    __half* __restrict__ Ch, __half* __restrict__ Cl,
    int outmode, float outscale, char* sm) {
    const uint32_t sbase = smem_u32(sm);
    float* sbias = (float*)sm;

    const int tid = threadIdx.x;
    const int wid = tid >> 5, lane = tid & 31;
    const int n0 = blockIdx.x * 128, m0 = blockIdx.y * 128;

    if (tid < 128) sbias[tid] = bias[n0 + tid];

    const int wm = (wid & 3) * 32;
    const int wn = (wid >> 2) * 64;

    float acc[2][8][4];
#pragma unroll
    for (int mt = 0; mt < 2; mt++)
#pragma unroll
        for (int nt = 0; nt < 8; nt++)
#pragma unroll
            for (int e = 0; e < 4; e++) acc[mt][nt][e] = 0.f;

    const int cr = tid >> 1;                  // row 0..127
    const int hcE = (tid & 1) * 16;           // element offset within 32-chunk
    const int localr = lane & 7, sel = lane >> 3;

    const __half* rowA_h = Ah + (size_t)(m0 + cr) * DD + hcE;
    const __half* rowA_l = Al + (size_t)(m0 + cr) * DD + hcE;
    const __half* rowB_h = Bh + (size_t)(n0 + cr) * DD + hcE;

#define G_STAGE(c, s)                                                       \
    do {                                                                    \
        const uint32_t stb = sbase + G_ST(s);                               \
        _Pragma("unroll")                                                   \
        for (int j = 0; j < 2; j++) {                                       \
            uint32_t off = SWZ64((uint32_t)(cr * 64 + hcE * 2 + 16 * j));   \
            CPA16(stb + G_AH + off, rowA_h + (size_t)(c) * 32 + 8 * j, 16); \
            CPA16(stb + G_AL + off, rowA_l + (size_t)(c) * 32 + 8 * j, 16); \
            CPA16(stb + G_BH + off, rowB_h + (size_t)(c) * 32 + 8 * j, 16); \
        }                                                                   \
        CPA_COMMIT();                                                       \
    } while (0)

    G_STAGE(0, 0);
    G_STAGE(1, 1);
    G_STAGE(2, 2);

    for (int c = 0; c < NCHUNK; c++) {
        const int s = c & 3;
        if (c + 2 < NCHUNK) CPA_WAIT2();
        else if (c + 1 < NCHUNK) CPA_WAIT1();
        else CPA_WAIT0();
        __syncthreads();
        if (c + 3 < NCHUNK) G_STAGE(c + 3, (c + 3) & 3);

        const uint32_t stb = sbase + G_ST(s);
#pragma unroll
        for (int kk = 0; kk < 32; kk += 16) {
            uint32_t ah[2][4], al[2][4];
#pragma unroll
            for (int mt = 0; mt < 2; mt++) {
                const int row = wm + mt * 16 + localr + (sel & 1) * 8;
                const int kb = kk + (sel >> 1) * 8;
                const uint32_t off = SWZ64((uint32_t)(row * 64 + kb * 2));
                LDSM_X4(ah[mt][0], ah[mt][1], ah[mt][2], ah[mt][3],
                        stb + G_AH + off);
                LDSM_X4(al[mt][0], al[mt][1], al[mt][2], al[mt][3],
                        stb + G_AL + off);
            }
            uint32_t bh[8][2];
#pragma unroll
            for (int np = 0; np < 4; np++) {
                const int row = wn + np * 16 + (sel >> 1) * 8 + localr;
                const int kb = kk + (sel & 1) * 8;
                const uint32_t off = SWZ64((uint32_t)(row * 64 + kb * 2));
                uint32_t t0, t1, t2, t3;
                LDSM_X4(t0, t1, t2, t3, stb + G_BH + off);
                bh[2 * np][0] = t0; bh[2 * np][1] = t1;
                bh[2 * np + 1][0] = t2; bh[2 * np + 1][1] = t3;
            }
#pragma unroll
            for (int mt = 0; mt < 2; mt++)
#pragma unroll
                for (int nt = 0; nt < 8; nt++)
                    MMA16816(acc[mt][nt], ah[mt], bh[nt]);
#pragma unroll
            for (int mt = 0; mt < 2; mt++)
#pragma unroll
                for (int nt = 0; nt < 8; nt++)
                    MMA16816(acc[mt][nt], al[mt], bh[nt]);
        }
    }

    const int er = lane >> 2;
    const int ec = (lane & 3) * 2;
#pragma unroll
    for (int mt = 0; mt < 2; mt++) {
#pragma unroll
        for (int nt = 0; nt < 8; nt++) {
            const int ct = wn + nt * 8 + ec;
            const int row0 = m0 + wm + mt * 16 + er;
            float x0 = (acc[mt][nt][0] + sbias[ct]) * outscale;
            float x1 = (acc[mt][nt][1] + sbias[ct + 1]) * outscale;
            float x2 = (acc[mt][nt][2] + sbias[ct]) * outscale;
            float x3 = (acc[mt][nt][3] + sbias[ct + 1]) * outscale;
            const size_t i0 = (size_t)row0 * DD + n0 + ct;
            const size_t i1 = (size_t)(row0 + 8) * DD + n0 + ct;
            if (outmode == 0) {
                float2 v0 = {x0, x1}, v1 = {x2, x3};
                *(float2*)&C[i0] = v0;
                *(float2*)&C[i1] = v1;
            } else if (outmode == 1) {
                uint32_t h0, l0u, h1, l1u;
                split2h(x0, x1, h0, l0u);
                split2h(x2, x3, h1, l1u);
                *(uint32_t*)&Ch[i0] = h0;
                *(uint32_t*)&Cl[i0] = l0u;
                *(uint32_t*)&Ch[i1] = h1;
                *(uint32_t*)&Cl[i1] = l1u;
            } else {
                *(uint32_t*)&Ch[i0] = packh(x0, x1);
                *(uint32_t*)&Ch[i1] = packh(x2, x3);
            }
        }
    }
#undef G_STAGE
}

// Fused Q/K/V projections: blockIdx.z selects weight/bias/output.
// z==0 (Q): hi/lo out, pre-scaled by SC2. z==1,2 (K,V): hi only.
struct QKVArgs {
    const __half* Bh[3];
    const float* bias[3];
    __half* Ch[3];
    __half* Cl;   // Q lo only
};

__global__ __launch_bounds__(256, 2)
void gemm_qkv(const __half* __restrict__ Ah,
              const __half* __restrict__ Al, QKVArgs a) {
    extern __shared__ char sm[];
    const int w = blockIdx.z;
    gemm_core(Ah, Al, a.Bh[w], a.bias[w], nullptr,
              a.Ch[w], (w == 0) ? a.Cl : nullptr,
              (w == 0) ? 1 : 2, (w == 0) ? SC2 : 1.0f, sm);
}

__global__ __launch_bounds__(256, 2)
void gemm_out(const __half* __restrict__ Ah,
              const __half* __restrict__ Al,
              const __half* __restrict__ Bh,
              const float* __restrict__ bias, float* __restrict__ C) {
    extern __shared__ char sm[];
    gemm_core(Ah, Al, Bh, bias, C, nullptr, nullptr, 0, 1.0f, sm);
}

// ===========================================================================
// mma.sync sliding-window flash attention, fp16 2-product, 3-stage cp.async,
// online softmax (exp2 domain; Q pre-scaled so scores are already in it),
// interior-tile mask fast path, underflow-based masking.
// CTA = 128 queries x 1 head, 8 warps (16 q-rows each).
// ===========================================================================
#define A_QH 0
#define A_QL 16384
#define A_ST(s) (32768 + (s) * 16384)
#define A_KH 0
#define A_VH 8192
#define ATT_SMEM (32768 + 3 * 16384)

__global__ __launch_bounds__(256, 2)
void attn_mma(const __half* __restrict__ Qh,
              const __half* __restrict__ Ql,
              const __half* __restrict__ Kh,
              const __half* __restrict__ Vh,
              __half* __restrict__ Oh,
              __half* __restrict__ Ol) {
    extern __shared__ char sm[];
    const uint32_t sbase = smem_u32(sm);

    const int tid = threadIdx.x;
    const int wid = tid >> 5, lane = tid & 31;
    const int qs = blockIdx.x * 128;
    const int hoff = blockIdx.y * HDIM;
    const int localr = lane & 7, sel = lane >> 3;

    // ---- stage Q tile (128 x 64 fp16 hi/lo), swizzled 128B rows ----
    {
        const int r = tid >> 1;
        const int half = (tid & 1) * 32;
        const size_t g = (size_t)(qs + r) * DD + hoff + half;
#pragma unroll
        for (int j = 0; j < 4; j++) {
            uint32_t off = SWZ((uint32_t)(r * 128 + (half + 8 * j) * 2));
            *(uint4*)(sm + A_QH + off) = *(const uint4*)&Qh[g + 8 * j];
            *(uint4*)(sm + A_QL + off) = *(const uint4*)&Ql[g + 8 * j];
        }
    }

    const int t0v = max(0, (512 - qs + 63) / 64);
    const int t1v = min(18, (SS + 512 - qs) / 64);

    const int svr = tid >> 2;
    const int svc = (tid & 3) * 16;

#define A_STAGE(t, s)                                                       \
    do {                                                                    \
        const int kabs_ = qs - 512 + 64 * (t) + svr;                        \
        const size_t g_ = (size_t)kabs_ * DD + hoff + svc;                  \
        const uint32_t stb_ = sbase + A_ST(s);                              \
        _Pragma("unroll")                                                   \
        for (int j = 0; j < 2; j++) {                                       \
            uint32_t off = SWZ((uint32_t)(svr * 128 + (svc + 8 * j) * 2));  \
            CPA16(stb_ + A_KH + off, &Kh[g_ + 8 * j], 16u);                 \
            CPA16(stb_ + A_VH + off, &Vh[g_ + 8 * j], 16u);                 \
        }                                                                   \
        CPA_COMMIT();                                                       \
    } while (0)

    const int q0 = qs + 16 * wid + (lane >> 2);
    const int q1 = q0 + 8;

    float m0 = -1e30f, m1 = -1e30f, l0 = 0.f, l1 = 0.f;
    float oacc[8][4];
#pragma unroll
    for (int nt = 0; nt < 8; nt++)
#pragma unroll
        for (int e = 0; e < 4; e++) oacc[nt][e] = 0.f;

    A_STAGE(t0v, 0);
    if (t0v + 1 < t1v) A_STAGE(t0v + 1, 1);

    for (int t = t0v; t < t1v; t++) {
        const int i = t - t0v;
        const int s = i % 3;
        const int kt = qs - 512 + 64 * t;
        if (t + 1 < t1v) CPA_WAIT1(); else CPA_WAIT0();
        __syncthreads();
        if (t + 2 < t1v) A_STAGE(t + 2, (i + 2) % 3);

        const uint32_t stb = sbase + A_ST(s);

        // ---- QK^T: S (16q x 64k per warp), 2 product passes ----
        float sacc[8][4];
#pragma unroll
        for (int nt = 0; nt < 8; nt++)
#pragma unroll
            for (int e = 0; e < 4; e++) sacc[nt][e] = 0.f;

#pragma unroll
        for (int kk = 0; kk < 64; kk += 16) {
            uint32_t qhf[4], qlf[4];
            {
                const int row = 16 * wid + localr + (sel & 1) * 8;
                const int kb = kk + (sel >> 1) * 8;
                const uint32_t off = SWZ((uint32_t)(row * 128 + kb * 2));
                LDSM_X4(qhf[0], qhf[1], qhf[2], qhf[3], sbase + A_QH + off);
                LDSM_X4(qlf[0], qlf[1], qlf[2], qlf[3], sbase + A_QL + off);
            }
            uint32_t khf[8][2];
#pragma unroll
            for (int np = 0; np < 4; np++) {
                const int row = np * 16 + (sel >> 1) * 8 + localr;
                const int kb = kk + (sel & 1) * 8;
                const uint32_t off = SWZ((uint32_t)(row * 128 + kb * 2));
                uint32_t t0r, t1r, t2r, t3r;
                LDSM_X4(t0r, t1r, t2r, t3r, stb + A_KH + off);
                khf[2 * np][0] = t0r; khf[2 * np][1] = t1r;
                khf[2 * np + 1][0] = t2r; khf[2 * np + 1][1] = t3r;
            }
#pragma unroll
            for (int nt = 0; nt < 8; nt++)
                MMA16816(sacc[nt], qhf, khf[nt]);
#pragma unroll
            for (int nt = 0; nt < 8; nt++)
                MMA16816(sacc[nt], qlf, khf[nt]);
        }

        // ---- window mask (edge tiles only) + row max ----
        float mx0 = -1e30f, mx1 = -1e30f;
        if (t < 2 || t > 15) {
            const int cb = kt + 2 * (lane & 3);
#pragma unroll
            for (int nt = 0; nt < 8; nt++) {
#pragma unroll
                for (int e = 0; e < 2; e++) {
                    const int kabs = cb + 8 * nt + e;
                    float s0 = ((kabs >= q0 - 512) & (kabs < q0 + 512))
                                   ? sacc[nt][e] : -1e30f;
                    float s1 = ((kabs >= q1 - 512) & (kabs < q1 + 512))
                                   ? sacc[nt][e + 2] : -1e30f;
                    sacc[nt][e] = s0; sacc[nt][e + 2] = s1;
                    mx0 = fmaxf(mx0, s0); mx1 = fmaxf(mx1, s1);
                }
            }
        } else {
#pragma unroll
            for (int nt = 0; nt < 8; nt++) {
#pragma unroll
                for (int e = 0; e < 2; e++) {
                    mx0 = fmaxf(mx0, sacc[nt][e]);
                    mx1 = fmaxf(mx1, sacc[nt][e + 2]);
                }
            }
        }
        mx0 = fmaxf(mx0, __shfl_xor_sync(0xffffffffu, mx0, 1));
        mx0 = fmaxf(mx0, __shfl_xor_sync(0xffffffffu, mx0, 2));
        mx1 = fmaxf(mx1, __shfl_xor_sync(0xffffffffu, mx1, 1));
        mx1 = fmaxf(mx1, __shfl_xor_sync(0xffffffffu, mx1, 2));
        const float mn0 = fmaxf(m0, mx0), mn1 = fmaxf(m1, mx1);
        const float a0 = exp2f(m0 - mn0), a1 = exp2f(m1 - mn1);
        m0 = mn0; m1 = mn1;
        float rs0 = 0.f, rs1 = 0.f;
#pragma unroll
        for (int nt = 0; nt < 8; nt++) {
#pragma unroll
            for (int e = 0; e < 2; e++) {
                float p0 = exp2f(sacc[nt][e] - mn0);
                float p1 = exp2f(sacc[nt][e + 2] - mn1);
                rs0 += p0; rs1 += p1;
                sacc[nt][e] = p0; sacc[nt][e + 2] = p1;
            }
        }
        l0 = l0 * a0 + rs0;
        l1 = l1 * a1 + rs1;
#pragma unroll
        for (int nt = 0; nt < 8; nt++) {
            oacc[nt][0] *= a0; oacc[nt][1] *= a0;
            oacc[nt][2] *= a1; oacc[nt][3] *= a1;
        }

        // ---- PV: O += P * V, 2 product passes ----
#pragma unroll
        for (int kc = 0; kc < 4; kc++) {
            uint32_t pah[4], pal[4];
            split2h(sacc[2 * kc][0], sacc[2 * kc][1], pah[0], pal[0]);
            split2h(sacc[2 * kc][2], sacc[2 * kc][3], pah[1], pal[1]);
            split2h(sacc[2 * kc + 1][0], sacc[2 * kc + 1][1], pah[2], pal[2]);
            split2h(sacc[2 * kc + 1][2], sacc[2 * kc + 1][3], pah[3], pal[3]);

            uint32_t vhf[8][2];
#pragma unroll
            for (int ntp = 0; ntp < 4; ntp++) {
                const int key = 16 * kc + (sel & 1) * 8 + localr;
                const int dim = (2 * ntp + (sel >> 1)) * 8;
                const uint32_t off = SWZ((uint32_t)(key * 128 + dim * 2));
                uint32_t t0r, t1r, t2r, t3r;
                LDSM_X4_T(t0r, t1r, t2r, t3r, stb + A_VH + off);
                vhf[2 * ntp][0] = t0r; vhf[2 * ntp][1] = t1r;
                vhf[2 * ntp + 1][0] = t2r; vhf[2 * ntp + 1][1] = t3r;
            }
#pragma unroll
            for (int nt = 0; nt < 8; nt++)
                MMA16816(oacc[nt], pah, vhf[nt]);
#pragma unroll
            for (int nt = 0; nt < 8; nt++)
                MMA16816(oacc[nt], pal, vhf[nt]);
        }
    }

    // ---- epilogue: normalize, blend weight, write fp16 hi/lo ----
    l0 += __shfl_xor_sync(0xffffffffu, l0, 1);
    l0 += __shfl_xor_sync(0xffffffffu, l0, 2);
    l1 += __shfl_xor_sync(0xffffffffu, l1, 1);
    l1 += __shfl_xor_sync(0xffffffffu, l1, 2);
    float w0 = 1.f, w1 = 1.f;
    if (q0 >= SS - 128) w0 = 1.f + (float)(q0 - (SS - 128)) * (1.f / 127.f);
    if (q1 >= SS - 128) w1 = 1.f + (float)(q1 - (SS - 128)) * (1.f / 127.f);
    const float sc0 = w0 / l0, sc1 = w1 / l1;
    const int ec = 2 * (lane & 3);
#pragma unroll
    for (int nt = 0; nt < 8; nt++) {
        const size_t i0 = (size_t)q0 * DD + hoff + 8 * nt + ec;
        const size_t i1 = (size_t)q1 * DD + hoff + 8 * nt + ec;
        uint32_t h0, l0u, h1, l1u;
        split2h(oacc[nt][0] * sc0, oacc[nt][1] * sc0, h0, l0u);
        split2h(oacc[nt][2] * sc1, oacc[nt][3] * sc1, h1, l1u);
        *(uint32_t*)&Oh[i0] = h0;
        *(uint32_t*)&Ol[i0] = l0u;
        *(uint32_t*)&Oh[i1] = h1;
        *(uint32_t*)&Ol[i1] = l1u;
    }
}

// ===========================================================================
extern "C" void kernel_launch(void* const* d_in, const int* in_sizes, int n_in,
                              void* d_out, int out_size) {
    const float* x = nullptr;
    const float* Wm[4] = {nullptr, nullptr, nullptr, nullptr};
    const float* bm[4] = {nullptr, nullptr, nullptr, nullptr};
    int nw = 0, nb = 0;
    for (int i = 0; i < n_in; i++) {
        const float* p = (const float*)d_in[i];
        if (in_sizes[i] == SS * DD) x = p;
        else if (in_sizes[i] == DD * DD) { if (nw < 4) Wm[nw++] = p; }
        else if (in_sizes[i] == DD) { if (nb < 4) bm[nb++] = p; }
    }
    float* out = (float*)d_out;

    __half *xh, *xl, *Wh, *Qh, *Ql, *Kh, *Vh, *Oh, *Ol;
    cudaGetSymbolAddress((void**)&xh, g_xh);
    cudaGetSymbolAddress((void**)&xl, g_xl);
    cudaGetSymbolAddress((void**)&Wh, g_Wh);
    cudaGetSymbolAddress((void**)&Qh, g_Qh);
    cudaGetSymbolAddress((void**)&Ql, g_Ql);
    cudaGetSymbolAddress((void**)&Kh, g_Kh);
    cudaGetSymbolAddress((void**)&Vh, g_Vh);
    cudaGetSymbolAddress((void**)&Oh, g_Oh);
    cudaGetSymbolAddress((void**)&Ol, g_Ol);

    // ---- fused split: x hi/lo + W hi (one launch) ----
    const int NTOT = NX8 + 4 * NW8;
    split_all<<<(NTOT + 255) / 256, 256>>>(x, Wm[0], Wm[1], Wm[2], Wm[3],
                                           xh, xl, Wh);

    cudaFuncSetAttribute(gemm_qkv, cudaFuncAttributeMaxDynamicSharedMemorySize,
                         GEMM_SMEM);
    cudaFuncSetAttribute(gemm_out, cudaFuncAttributeMaxDynamicSharedMemorySize,
                         GEMM_SMEM);
    cudaFuncSetAttribute(attn_mma, cudaFuncAttributeMaxDynamicSharedMemorySize,
                         ATT_SMEM);

    // ---- fused Q/K/V projections ----
    QKVArgs qa;
    qa.Bh[0] = Wh;
    qa.Bh[1] = Wh + (size_t)1 * DD * DD;
    qa.Bh[2] = Wh + (size_t)2 * DD * DD;
    qa.bias[0] = bm[0]; qa.bias[1] = bm[1]; qa.bias[2] = bm[2];
    qa.Ch[0] = Qh; qa.Ch[1] = Kh; qa.Ch[2] = Vh;
    qa.Cl = Ql;

    dim3 qkvgrid(DD / 128, SS / 128, 3);
    gemm_qkv<<<qkvgrid, 256, GEMM_SMEM>>>(xh, xl, qa);

    attn_mma<<<dim3(SS / 128, HH), 256, ATT_SMEM>>>(Qh, Ql, Kh, Vh, Oh, Ol);

    dim3 ogrid(DD / 128, SS / 128);
    gemm_out<<<ogrid, 256, GEMM_SMEM>>>(Oh, Ol, Wh + (size_t)3 * DD * DD,
                                        bm[3], out);
}

// round 17
// speedup vs baseline: 1.5823x; 1.0612x over previous
#include <cuda_runtime.h>
#include <cuda_fp16.h>
#include <stdint.h>
#include <math.h>

#define SS 8192
#define DD 1024
#define HH 16
#define HDIM 64

// ---- scratch: fp16 operands (static device arrays) ----
__device__ __half g_xh[SS * DD], g_xl[SS * DD];
__device__ __half g_Wh[4][DD * DD];            // weights: hi only
__device__ __half g_Qh[SS * DD], g_Ql[SS * DD];
__device__ __half g_Kh[SS * DD];               // K: hi only
__device__ __half g_Vh[SS * DD];               // V: hi only
__device__ __half g_Oh[SS * DD], g_Ol[SS * DD];

// ===========================================================================
// PTX helpers (baseline ISA: ldmatrix + mma.sync + cp.async, sm_80+)
// ===========================================================================
__device__ __forceinline__ uint32_t smem_u32(const void* p) {
    uint32_t a;
    asm("{ .reg .u64 t; cvta.to.shared.u64 t, %1; cvt.u32.u64 %0, t; }"
        : "=r"(a) : "l"(p));
    return a;
}

#define LDSM_X4(r0, r1, r2, r3, addr)                                       \
    asm volatile(                                                           \
        "ldmatrix.sync.aligned.m8n8.x4.shared.b16 {%0, %1, %2, %3}, [%4];"  \
        : "=r"(r0), "=r"(r1), "=r"(r2), "=r"(r3) : "r"(addr))

#define LDSM_X4_T(r0, r1, r2, r3, addr)                                     \
    asm volatile(                                                           \
        "ldmatrix.sync.aligned.m8n8.x4.trans.shared.b16 {%0, %1, %2, %3}, [%4];" \
        : "=r"(r0), "=r"(r1), "=r"(r2), "=r"(r3) : "r"(addr))

#define MMA16816(d, a, b)                                                   \
    asm volatile(                                                           \
        "mma.sync.aligned.m16n8k16.row.col.f32.f16.f16.f32 "                \
        "{%0, %1, %2, %3}, {%4, %5, %6, %7}, {%8, %9}, {%0, %1, %2, %3};"   \
        : "+f"((d)[0]), "+f"((d)[1]), "+f"((d)[2]), "+f"((d)[3])            \
        : "r"((a)[0]), "r"((a)[1]), "r"((a)[2]), "r"((a)[3]),               \
          "r"((b)[0]), "r"((b)[1]))

#define CPA16(dst, src, sz)                                                 \
    asm volatile("cp.async.cg.shared.global [%0], [%1], 16, %2;"            \
                 :: "r"(dst), "l"(src), "r"(sz))
#define CPA_COMMIT() asm volatile("cp.async.commit_group;" ::: "memory")
#define CPA_WAIT2()  asm volatile("cp.async.wait_group 2;" ::: "memory")
#define CPA_WAIT1()  asm volatile("cp.async.wait_group 1;" ::: "memory")
#define CPA_WAIT0()  asm volatile("cp.async.wait_group 0;" ::: "memory")

#define SWZ(o)   ((o) ^ (((o) >> 3) & 0x70))   // 128B rows
#define SWZ64(o) ((o) ^ (((o) >> 3) & 0x30))   // 64B rows

// Single-instruction fp16x2 pack, round-to-nearest.
__device__ __forceinline__ uint32_t packh(float x, float y) {
    __half2 t = __floats2half2_rn(x, y);
    return *(uint32_t*)&t;
}
// hi/lo split of a float pair into fp16: h = rn(x,y); l = rn(residues).
__device__ __forceinline__ void split2h(float x, float y,
                                        uint32_t& h, uint32_t& l) {
    h = packh(x, y);
    __half2 hv = *(__half2*)&h;
    l = packh(x - __low2float(hv), y - __high2float(hv));
}

#define SC2 (0.125f * 1.44269504f)   // score scale folded with log2(e)

// ===========================================================================
// Fused fp32 -> fp16 split: x -> hi/lo, W0..3 -> hi only (one launch).
// ===========================================================================
#define NX8 (SS * DD / 8)
#define NW8 (DD * DD / 8)

__global__ void split_all(const float* __restrict__ x,
                          const float* __restrict__ w0,
                          const float* __restrict__ w1,
                          const float* __restrict__ w2,
                          const float* __restrict__ w3,
                          __half* __restrict__ xh,
                          __half* __restrict__ xl,
                          __half* __restrict__ Wh) {
    int idx = blockIdx.x * blockDim.x + threadIdx.x;
    if (idx < NX8) {
        const float4* p = (const float4*)x + (size_t)idx * 2;
        float4 v0 = p[0], v1 = p[1];
        uint32_t h[4], l[4];
        split2h(v0.x, v0.y, h[0], l[0]);
        split2h(v0.z, v0.w, h[1], l[1]);
        split2h(v1.x, v1.y, h[2], l[2]);
        split2h(v1.z, v1.w, h[3], l[3]);
        ((uint4*)xh)[idx] = *(uint4*)h;
        ((uint4*)xl)[idx] = *(uint4*)l;
    } else if (idx < NX8 + 4 * NW8) {
        int r = idx - NX8;
        int w = r >> 17;           // / NW8 (2^17)
        int o = r & (NW8 - 1);
        const float* ws[4] = {w0, w1, w2, w3};
        const float4* p = (const float4*)ws[w] + (size_t)o * 2;
        float4 v0 = p[0], v1 = p[1];
        uint32_t h[4];
        h[0] = packh(v0.x, v0.y);
        h[1] = packh(v0.z, v0.w);
        h[2] = packh(v1.x, v1.y);
        h[3] = packh(v1.z, v1.w);
        ((uint4*)(Wh + (size_t)w * DD * DD))[o] = *(uint4*)h;
    }
}

// ===========================================================================
// Shared GEMM core: mma.sync fp16 2-product ((Ah+Al)*Bh), fp32 accum,
// K-chunk 32 (64B rows, SW64), 4-stage cp.async (distance 3), occ 2.
//   C[m,n] = sum_k A[m,k]*W[n,k] + bias[n]
// CTA 128x128, 256 threads (8 warps 32m x 64n).
// outmode: 0 = fp32 C, 1 = fp16 hi/lo pair (scaled), 2 = fp16 hi only.
// ===========================================================================
#define G_ST(s)  (1024 + (s) * 24576)
#define G_AH 0
#define G_AL 8192
#define G_BH 16384
#define GEMM_SMEM (1024 + 4 * 24576)
#define NCHUNK 32

__device__ __forceinline__ void gemm_core(
    const __half* __restrict__ Ah, const __half* __restrict__ Al,
    const __half* __restrict__ Bh,
    const float* __restrict__ bias, float* __restrict__ C,
    __half* __restrict__ Ch, __half* __restrict__ Cl,
    int outmode, float outscale, char* sm) {
    const uint32_t sbase = smem_u32(sm);
    float* sbias = (float*)sm;

    const int tid = threadIdx.x;
    const int wid = tid >> 5, lane = tid & 31;
    const int n0 = blockIdx.x * 128, m0 = blockIdx.y * 128;

    if (tid < 128) sbias[tid] = bias[n0 + tid];

    const int wm = (wid & 3) * 32;
    const int wn = (wid >> 2) * 64;

    float acc[2][8][4];
#pragma unroll
    for (int mt = 0; mt < 2; mt++)
#pragma unroll
        for (int nt = 0; nt < 8; nt++)
#pragma unroll
            for (int e = 0; e < 4; e++) acc[mt][nt][e] = 0.f;

    const int cr = tid >> 1;                  // row 0..127
    const int hcE = (tid & 1) * 16;           // element offset within 32-chunk
    const int localr = lane & 7, sel = lane >> 3;

    const __half* rowA_h = Ah + (size_t)(m0 + cr) * DD + hcE;
    const __half* rowA_l = Al + (size_t)(m0 + cr) * DD + hcE;
    const __half* rowB_h = Bh + (size_t)(n0 + cr) * DD + hcE;

#define G_STAGE(c, s)                                                       \
    do {                                                                    \
        const uint32_t stb = sbase + G_ST(s);                               \
        _Pragma("unroll")                                                   \
        for (int j = 0; j < 2; j++) {                                       \
            uint32_t off = SWZ64((uint32_t)(cr * 64 + hcE * 2 + 16 * j));   \
            CPA16(stb + G_AH + off, rowA_h + (size_t)(c) * 32 + 8 * j, 16); \
            CPA16(stb + G_AL + off, rowA_l + (size_t)(c) * 32 + 8 * j, 16); \
            CPA16(stb + G_BH + off, rowB_h + (size_t)(c) * 32 + 8 * j, 16); \
        }                                                                   \
        CPA_COMMIT();                                                       \
    } while (0)

    G_STAGE(0, 0);
    G_STAGE(1, 1);
    G_STAGE(2, 2);

    for (int c = 0; c < NCHUNK; c++) {
        const int s = c & 3;
        if (c + 2 < NCHUNK) CPA_WAIT2();
        else if (c + 1 < NCHUNK) CPA_WAIT1();
        else CPA_WAIT0();
        __syncthreads();
        if (c + 3 < NCHUNK) G_STAGE(c + 3, (c + 3) & 3);

        const uint32_t stb = sbase + G_ST(s);
#pragma unroll
        for (int kk = 0; kk < 32; kk += 16) {
            uint32_t ah[2][4], al[2][4];
#pragma unroll
            for (int mt = 0; mt < 2; mt++) {
                const int row = wm + mt * 16 + localr + (sel & 1) * 8;
                const int kb = kk + (sel >> 1) * 8;
                const uint32_t off = SWZ64((uint32_t)(row * 64 + kb * 2));
                LDSM_X4(ah[mt][0], ah[mt][1], ah[mt][2], ah[mt][3],
                        stb + G_AH + off);
                LDSM_X4(al[mt][0], al[mt][1], al[mt][2], al[mt][3],
                        stb + G_AL + off);
            }
            uint32_t bh[8][2];
#pragma unroll
            for (int np = 0; np < 4; np++) {
                const int row = wn + np * 16 + (sel >> 1) * 8 + localr;
                const int kb = kk + (sel & 1) * 8;
                const uint32_t off = SWZ64((uint32_t)(row * 64 + kb * 2));
                uint32_t t0, t1, t2, t3;
                LDSM_X4(t0, t1, t2, t3, stb + G_BH + off);
                bh[2 * np][0] = t0; bh[2 * np][1] = t1;
                bh[2 * np + 1][0] = t2; bh[2 * np + 1][1] = t3;
            }
#pragma unroll
            for (int mt = 0; mt < 2; mt++)
#pragma unroll
                for (int nt = 0; nt < 8; nt++)
                    MMA16816(acc[mt][nt], ah[mt], bh[nt]);
#pragma unroll
            for (int mt = 0; mt < 2; mt++)
#pragma unroll
                for (int nt = 0; nt < 8; nt++)
                    MMA16816(acc[mt][nt], al[mt], bh[nt]);
        }
    }

    const int er = lane >> 2;
    const int ec = (lane & 3) * 2;
#pragma unroll
    for (int mt = 0; mt < 2; mt++) {
#pragma unroll
        for (int nt = 0; nt < 8; nt++) {
            const int ct = wn + nt * 8 + ec;
            const int row0 = m0 + wm + mt * 16 + er;
            float x0 = (acc[mt][nt][0] + sbias[ct]) * outscale;
            float x1 = (acc[mt][nt][1] + sbias[ct + 1]) * outscale;
            float x2 = (acc[mt][nt][2] + sbias[ct]) * outscale;
            float x3 = (acc[mt][nt][3] + sbias[ct + 1]) * outscale;
            const size_t i0 = (size_t)row0 * DD + n0 + ct;
            const size_t i1 = (size_t)(row0 + 8) * DD + n0 + ct;
            if (outmode == 0) {
                float2 v0 = {x0, x1}, v1 = {x2, x3};
                *(float2*)&C[i0] = v0;
                *(float2*)&C[i1] = v1;
            } else if (outmode == 1) {
                uint32_t h0, l0u, h1, l1u;
                split2h(x0, x1, h0, l0u);
                split2h(x2, x3, h1, l1u);
                *(uint32_t*)&Ch[i0] = h0;
                *(uint32_t*)&Cl[i0] = l0u;
                *(uint32_t*)&Ch[i1] = h1;
                *(uint32_t*)&Cl[i1] = l1u;
            } else {
                *(uint32_t*)&Ch[i0] = packh(x0, x1);
                *(uint32_t*)&Ch[i1] = packh(x2, x3);
            }
        }
    }
#undef G_STAGE
}

// Fused Q/K/V projections: blockIdx.z selects weight/bias/output.
// z==0 (Q): hi/lo out, pre-scaled by SC2. z==1,2 (K,V): hi only.
struct QKVArgs {
    const __half* Bh[3];
    const float* bias[3];
    __half* Ch[3];
    __half* Cl;   // Q lo only
};

__global__ __launch_bounds__(256, 2)
void gemm_qkv(const __half* __restrict__ Ah,
              const __half* __restrict__ Al, QKVArgs a) {
    extern __shared__ char sm[];
    const int w = blockIdx.z;
    gemm_core(Ah, Al, a.Bh[w], a.bias[w], nullptr,
              a.Ch[w], (w == 0) ? a.Cl : nullptr,
              (w == 0) ? 1 : 2, (w == 0) ? SC2 : 1.0f, sm);
}

__global__ __launch_bounds__(256, 2)
void gemm_out(const __half* __restrict__ Ah,
              const __half* __restrict__ Al,
              const __half* __restrict__ Bh,
              const float* __restrict__ bias, float* __restrict__ C) {
    extern __shared__ char sm[];
    gemm_core(Ah, Al, Bh, bias, C, nullptr, nullptr, 0, 1.0f, sm);
}

// ===========================================================================
// mma.sync sliding-window flash attention, fp16, 3-stage cp.async,
// online softmax (exp2 domain; Q pre-scaled), interior-tile mask fast path,
// underflow-based masking. QK: 2 products (Q hi/lo); PV: 1 product (P hi).
// CTA = 128 queries x 1 head, 8 warps (16 q-rows each).
// ===========================================================================
#define A_QH 0
#define A_QL 16384
#define A_ST(s) (32768 + (s) * 16384)
#define A_KH 0
#define A_VH 8192
#define ATT_SMEM (32768 + 3 * 16384)

__global__ __launch_bounds__(256, 2)
void attn_mma(const __half* __restrict__ Qh,
              const __half* __restrict__ Ql,
              const __half* __restrict__ Kh,
              const __half* __restrict__ Vh,
              __half* __restrict__ Oh,
              __half* __restrict__ Ol) {
    extern __shared__ char sm[];
    const uint32_t sbase = smem_u32(sm);

    const int tid = threadIdx.x;
    const int wid = tid >> 5, lane = tid & 31;
    const int qs = blockIdx.x * 128;
    const int hoff = blockIdx.y * HDIM;
    const int localr = lane & 7, sel = lane >> 3;

    // ---- stage Q tile (128 x 64 fp16 hi/lo), swizzled 128B rows ----
    {
        const int r = tid >> 1;
        const int half = (tid & 1) * 32;
        const size_t g = (size_t)(qs + r) * DD + hoff + half;
#pragma unroll
        for (int j = 0; j < 4; j++) {
            uint32_t off = SWZ((uint32_t)(r * 128 + (half + 8 * j) * 2));
            *(uint4*)(sm + A_QH + off) = *(const uint4*)&Qh[g + 8 * j];
            *(uint4*)(sm + A_QL + off) = *(const uint4*)&Ql[g + 8 * j];
        }
    }

    const int t0v = max(0, (512 - qs + 63) / 64);
    const int t1v = min(18, (SS + 512 - qs) / 64);

    const int svr = tid >> 2;
    const int svc = (tid & 3) * 16;

#define A_STAGE(t, s)                                                       \
    do {                                                                    \
        const int kabs_ = qs - 512 + 64 * (t) + svr;                        \
        const size_t g_ = (size_t)kabs_ * DD + hoff + svc;                  \
        const uint32_t stb_ = sbase + A_ST(s);                              \
        _Pragma("unroll")                                                   \
        for (int j = 0; j < 2; j++) {                                       \
            uint32_t off = SWZ((uint32_t)(svr * 128 + (svc + 8 * j) * 2));  \
            CPA16(stb_ + A_KH + off, &Kh[g_ + 8 * j], 16u);                 \
            CPA16(stb_ + A_VH + off, &Vh[g_ + 8 * j], 16u);                 \
        }                                                                   \
        CPA_COMMIT();                                                       \
    } while (0)

    const int q0 = qs + 16 * wid + (lane >> 2);
    const int q1 = q0 + 8;

    float m0 = -1e30f, m1 = -1e30f, l0 = 0.f, l1 = 0.f;
    float oacc[8][4];
#pragma unroll
    for (int nt = 0; nt < 8; nt++)
#pragma unroll
        for (int e = 0; e < 4; e++) oacc[nt][e] = 0.f;

    A_STAGE(t0v, 0);
    if (t0v + 1 < t1v) A_STAGE(t0v + 1, 1);

    for (int t = t0v; t < t1v; t++) {
        const int i = t - t0v;
        const int s = i % 3;
        const int kt = qs - 512 + 64 * t;
        if (t + 1 < t1v) CPA_WAIT1(); else CPA_WAIT0();
        __syncthreads();
        if (t + 2 < t1v) A_STAGE(t + 2, (i + 2) % 3);

        const uint32_t stb = sbase + A_ST(s);

        // ---- QK^T: S (16q x 64k per warp), 2 product passes ----
        float sacc[8][4];
#pragma unroll
        for (int nt = 0; nt < 8; nt++)
#pragma unroll
            for (int e = 0; e < 4; e++) sacc[nt][e] = 0.f;

#pragma unroll
        for (int kk = 0; kk < 64; kk += 16) {
            uint32_t qhf[4], qlf[4];
            {
                const int row = 16 * wid + localr + (sel & 1) * 8;
                const int kb = kk + (sel >> 1) * 8;
                const uint32_t off = SWZ((uint32_t)(row * 128 + kb * 2));
                LDSM_X4(qhf[0], qhf[1], qhf[2], qhf[3], sbase + A_QH + off);
                LDSM_X4(qlf[0], qlf[1], qlf[2], qlf[3], sbase + A_QL + off);
            }
            uint32_t khf[8][2];
#pragma unroll
            for (int np = 0; np < 4; np++) {
                const int row = np * 16 + (sel >> 1) * 8 + localr;
                const int kb = kk + (sel & 1) * 8;
                const uint32_t off = SWZ((uint32_t)(row * 128 + kb * 2));
                uint32_t t0r, t1r, t2r, t3r;
                LDSM_X4(t0r, t1r, t2r, t3r, stb + A_KH + off);
                khf[2 * np][0] = t0r; khf[2 * np][1] = t1r;
                khf[2 * np + 1][0] = t2r; khf[2 * np + 1][1] = t3r;
            }
#pragma unroll
            for (int nt = 0; nt < 8; nt++)
                MMA16816(sacc[nt], qhf, khf[nt]);
#pragma unroll
            for (int nt = 0; nt < 8; nt++)
                MMA16816(sacc[nt], qlf, khf[nt]);
        }

        // ---- window mask (edge tiles only) + row max ----
        float mx0 = -1e30f, mx1 = -1e30f;
        if (t < 2 || t > 15) {
            const int cb = kt + 2 * (lane & 3);
#pragma unroll
            for (int nt = 0; nt < 8; nt++) {
#pragma unroll
                for (int e = 0; e < 2; e++) {
                    const int kabs = cb + 8 * nt + e;
                    float s0 = ((kabs >= q0 - 512) & (kabs < q0 + 512))
                                   ? sacc[nt][e] : -1e30f;
                    float s1 = ((kabs >= q1 - 512) & (kabs < q1 + 512))
                                   ? sacc[nt][e + 2] : -1e30f;
                    sacc[nt][e] = s0; sacc[nt][e + 2] = s1;
                    mx0 = fmaxf(mx0, s0); mx1 = fmaxf(mx1, s1);
                }
            }
        } else {
#pragma unroll
            for (int nt = 0; nt < 8; nt++) {
#pragma unroll
                for (int e = 0; e < 2; e++) {
                    mx0 = fmaxf(mx0, sacc[nt][e]);
                    mx1 = fmaxf(mx1, sacc[nt][e + 2]);
                }
            }
        }
        mx0 = fmaxf(mx0, __shfl_xor_sync(0xffffffffu, mx0, 1));
        mx0 = fmaxf(mx0, __shfl_xor_sync(0xffffffffu, mx0, 2));
        mx1 = fmaxf(mx1, __shfl_xor_sync(0xffffffffu, mx1, 1));
        mx1 = fmaxf(mx1, __shfl_xor_sync(0xffffffffu, mx1, 2));
        const float mn0 = fmaxf(m0, mx0), mn1 = fmaxf(m1, mx1);
        const float a0 = exp2f(m0 - mn0), a1 = exp2f(m1 - mn1);
        m0 = mn0; m1 = mn1;
        float rs0 = 0.f, rs1 = 0.f;
#pragma unroll
        for (int nt = 0; nt < 8; nt++) {
#pragma unroll
            for (int e = 0; e < 2; e++) {
                float p0 = exp2f(sacc[nt][e] - mn0);
                float p1 = exp2f(sacc[nt][e + 2] - mn1);
                rs0 += p0; rs1 += p1;
                sacc[nt][e] = p0; sacc[nt][e + 2] = p1;
            }
        }
        l0 = l0 * a0 + rs0;
        l1 = l1 * a1 + rs1;
#pragma unroll
        for (int nt = 0; nt < 8; nt++) {
            oacc[nt][0] *= a0; oacc[nt][1] *= a0;
            oacc[nt][2] *= a1; oacc[nt][3] *= a1;
        }

        // ---- PV: O += P * V, single product (P hi only) ----
#pragma unroll
        for (int kc = 0; kc < 4; kc++) {
            uint32_t pah[4];
            pah[0] = packh(sacc[2 * kc][0], sacc[2 * kc][1]);
            pah[1] = packh(sacc[2 * kc][2], sacc[2 * kc][3]);
            pah[2] = packh(sacc[2 * kc + 1][0], sacc[2 * kc + 1][1]);
            pah[3] = packh(sacc[2 * kc + 1][2], sacc[2 * kc + 1][3]);

            uint32_t vhf[8][2];
#pragma unroll
            for (int ntp = 0; ntp < 4; ntp++) {
                const int key = 16 * kc + (sel & 1) * 8 + localr;
                const int dim = (2 * ntp + (sel >> 1)) * 8;
                const uint32_t off = SWZ((uint32_t)(key * 128 + dim * 2));
                uint32_t t0r, t1r, t2r, t3r;
                LDSM_X4_T(t0r, t1r, t2r, t3r, stb + A_VH + off);
                vhf[2 * ntp][0] = t0r; vhf[2 * ntp][1] = t1r;
                vhf[2 * ntp + 1][0] = t2r; vhf[2 * ntp + 1][1] = t3r;
            }
#pragma unroll
            for (int nt = 0; nt < 8; nt++)
                MMA16816(oacc[nt], pah, vhf[nt]);
        }
    }

    // ---- epilogue: normalize, blend weight, write fp16 hi/lo ----
    l0 += __shfl_xor_sync(0xffffffffu, l0, 1);
    l0 += __shfl_xor_sync(0xffffffffu, l0, 2);
    l1 += __shfl_xor_sync(0xffffffffu, l1, 1);
    l1 += __shfl_xor_sync(0xffffffffu, l1, 2);
    float w0 = 1.f, w1 = 1.f;
    if (q0 >= SS - 128) w0 = 1.f + (float)(q0 - (SS - 128)) * (1.f / 127.f);
    if (q1 >= SS - 128) w1 = 1.f + (float)(q1 - (SS - 128)) * (1.f / 127.f);
    const float sc0 = w0 / l0, sc1 = w1 / l1;
    const int ec = 2 * (lane & 3);
#pragma unroll
    for (int nt = 0; nt < 8; nt++) {
        const size_t i0 = (size_t)q0 * DD + hoff + 8 * nt + ec;
        const size_t i1 = (size_t)q1 * DD + hoff + 8 * nt + ec;
        uint32_t h0, l0u, h1, l1u;
        split2h(oacc[nt][0] * sc0, oacc[nt][1] * sc0, h0, l0u);
        split2h(oacc[nt][2] * sc1, oacc[nt][3] * sc1, h1, l1u);
        *(uint32_t*)&Oh[i0] = h0;
        *(uint32_t*)&Ol[i0] = l0u;
        *(uint32_t*)&Oh[i1] = h1;
        *(uint32_t*)&Ol[i1] = l1u;
    }
}

// ===========================================================================
extern "C" void kernel_launch(void* const* d_in, const int* in_sizes, int n_in,
                              void* d_out, int out_size) {
    const float* x = nullptr;
    const float* Wm[4] = {nullptr, nullptr, nullptr, nullptr};
    const float* bm[4] = {nullptr, nullptr, nullptr, nullptr};
    int nw = 0, nb = 0;
    for (int i = 0; i < n_in; i++) {
        const float* p = (const float*)d_in[i];
        if (in_sizes[i] == SS * DD) x = p;
        else if (in_sizes[i] == DD * DD) { if (nw < 4) Wm[nw++] = p; }
        else if (in_sizes[i] == DD) { if (nb < 4) bm[nb++] = p; }
    }
    float* out = (float*)d_out;

    __half *xh, *xl, *Wh, *Qh, *Ql, *Kh, *Vh, *Oh, *Ol;
    cudaGetSymbolAddress((void**)&xh, g_xh);
    cudaGetSymbolAddress((void**)&xl, g_xl);
    cudaGetSymbolAddress((void**)&Wh, g_Wh);
    cudaGetSymbolAddress((void**)&Qh, g_Qh);
    cudaGetSymbolAddress((void**)&Ql, g_Ql);
    cudaGetSymbolAddress((void**)&Kh, g_Kh);
    cudaGetSymbolAddress((void**)&Vh, g_Vh);
    cudaGetSymbolAddress((void**)&Oh, g_Oh);
    cudaGetSymbolAddress((void**)&Ol, g_Ol);

    // ---- fused split: x hi/lo + W hi (one launch) ----
    const int NTOT = NX8 + 4 * NW8;
    split_all<<<(NTOT + 255) / 256, 256>>>(x, Wm[0], Wm[1], Wm[2], Wm[3],
                                           xh, xl, Wh);

    cudaFuncSetAttribute(gemm_qkv, cudaFuncAttributeMaxDynamicSharedMemorySize,
                         GEMM_SMEM);
    cudaFuncSetAttribute(gemm_out, cudaFuncAttributeMaxDynamicSharedMemorySize,
                         GEMM_SMEM);
    cudaFuncSetAttribute(attn_mma, cudaFuncAttributeMaxDynamicSharedMemorySize,
                         ATT_SMEM);

    // ---- fused Q/K/V projections ----
    QKVArgs qa;
    qa.Bh[0] = Wh;
    qa.Bh[1] = Wh + (size_t)1 * DD * DD;
    qa.Bh[2] = Wh + (size_t)2 * DD * DD;
    qa.bias[0] = bm[0]; qa.bias[1] = bm[1]; qa.bias[2] = bm[2];
    qa.Ch[0] = Qh; qa.Ch[1] = Kh; qa.Ch[2] = Vh;
    qa.Cl = Ql;

    dim3 qkvgrid(DD / 128, SS / 128, 3);
    gemm_qkv<<<qkvgrid, 256, GEMM_SMEM>>>(xh, xl, qa);

    attn_mma<<<dim3(SS / 128, HH), 256, ATT_SMEM>>>(Qh, Ql, Kh, Vh, Oh, Ol);

    dim3 ogrid(DD / 128, SS / 128);
    gemm_out<<<ogrid, 256, GEMM_SMEM>>>(Oh, Ol, Wh + (size_t)3 * DD * DD,
                                        bm[3], out);
}